// round 11
// baseline (speedup 1.0000x reference)
#include <cuda_runtime.h>
#include <math.h>
#include <stdint.h>

#define BB 4
#define LL 4096
#define CC 1024
#define NHH 16
#define CSS 16
#define HFF 64
#define HF4 256
#define NCC 256
#define MROWS (BB*LL)   // 16384
#define XSZ (BB*NHH*NCC*CSS*HFF)

// ---------------- device scratch -----------------
__device__ float g_X[3*XSZ];                 // [0]=XC, [1]=XB, [2]=XA (split layout)
__device__ float g_coef[BB*NHH*NCC*CSS];
__device__ float g_Z2b[(size_t)MROWS*CC];
__device__ float g_hsr[(size_t)MROWS*CC];
__device__ float g_WT[4][CC*CC];

// ---------------- helpers -----------------
__device__ __forceinline__ float to_tf32(float x){
    uint32_t u; asm("cvt.rna.tf32.f32 %0, %1;" : "=r"(u) : "f"(x));
    return __uint_as_float(u);
}
__device__ __forceinline__ uint32_t f2tf(float x){
    uint32_t u; asm("cvt.rna.tf32.f32 %0, %1;" : "=r"(u) : "f"(x));
    return u;
}
__device__ __forceinline__ void splitf(float v, uint32_t& h, uint32_t& l){
    h = f2tf(v);
    l = f2tf(v - __uint_as_float(h));
}
__device__ __forceinline__ float2 sp(float v){
    uint32_t h,l; splitf(v,h,l);
    return make_float2(__uint_as_float(h), __uint_as_float(l));
}
__device__ __forceinline__ uint32_t fu(float x){ return __float_as_uint(x); }
__device__ __forceinline__ void ldsm4(uint32_t* r, uint32_t addr){
    asm volatile("ldmatrix.sync.aligned.m8n8.x4.shared.b16 {%0,%1,%2,%3}, [%4];"
        : "=r"(r[0]),"=r"(r[1]),"=r"(r[2]),"=r"(r[3]) : "r"(addr));
}
__device__ __forceinline__ void mma_tf32(float* c, const uint32_t* a, uint32_t b0, uint32_t b1){
    asm volatile("mma.sync.aligned.m16n8k8.row.col.f32.tf32.tf32.f32 "
        "{%0,%1,%2,%3},{%4,%5,%6,%7},{%8,%9},{%0,%1,%2,%3};"
        : "+f"(c[0]),"+f"(c[1]),"+f"(c[2]),"+f"(c[3])
        : "r"(a[0]),"r"(a[1]),"r"(a[2]),"r"(a[3]),"r"(b0),"r"(b1));
}
__device__ __forceinline__ void mma3(float* c, const uint32_t* ah, const uint32_t* al,
                                     const uint32_t* bh, const uint32_t* bl){
    mma_tf32(c, ah, bh[0], bh[1]);
    mma_tf32(c, ah, bl[0], bl[1]);
    mma_tf32(c, al, bh[0], bh[1]);
}
// raw-split loaders (still used for W1 in P1)
__device__ __forceinline__ void ldBf(const float* S, int ld, int k0, int n0, int lane,
                                     uint32_t* bh, uint32_t* bl){
    int g = lane >> 2, tg = lane & 3;
    splitf(S[(k0+tg)*ld + n0+g],   bh[0], bl[0]);
    splitf(S[(k0+tg+4)*ld + n0+g], bh[1], bl[1]);
}
// paired loaders: S holds (hi,lo) float2 per logical element; ld = floats per row
__device__ __forceinline__ void ldAf_p(const float* S, int ld, int k0, int lane,
                                       uint32_t* ah, uint32_t* al){
    int g = lane >> 2, tg = lane & 3;
    float2 v0 = *(const float2*)&S[g*ld     + 2*(k0+tg)];
    float2 v1 = *(const float2*)&S[(g+8)*ld + 2*(k0+tg)];
    float2 v2 = *(const float2*)&S[g*ld     + 2*(k0+tg+4)];
    float2 v3 = *(const float2*)&S[(g+8)*ld + 2*(k0+tg+4)];
    ah[0]=fu(v0.x); al[0]=fu(v0.y);
    ah[1]=fu(v1.x); al[1]=fu(v1.y);
    ah[2]=fu(v2.x); al[2]=fu(v2.y);
    ah[3]=fu(v3.x); al[3]=fu(v3.y);
}
__device__ __forceinline__ void ldAfT_p(const float* S, int ld, int m0, int k0, int lane,
                                        uint32_t* ah, uint32_t* al){
    int g = lane >> 2, tg = lane & 3;
    float2 v0 = *(const float2*)&S[(k0+tg)*ld   + 2*(m0+g)];
    float2 v1 = *(const float2*)&S[(k0+tg)*ld   + 2*(m0+g+8)];
    float2 v2 = *(const float2*)&S[(k0+tg+4)*ld + 2*(m0+g)];
    float2 v3 = *(const float2*)&S[(k0+tg+4)*ld + 2*(m0+g+8)];
    ah[0]=fu(v0.x); al[0]=fu(v0.y);
    ah[1]=fu(v1.x); al[1]=fu(v1.y);
    ah[2]=fu(v2.x); al[2]=fu(v2.y);
    ah[3]=fu(v3.x); al[3]=fu(v3.y);
}
__device__ __forceinline__ void ldBf_p(const float* S, int ld, int k0, int n0, int lane,
                                       uint32_t* bh, uint32_t* bl){
    int g = lane >> 2, tg = lane & 3;
    float2 v0 = *(const float2*)&S[(k0+tg)*ld   + 2*(n0+g)];
    float2 v1 = *(const float2*)&S[(k0+tg+4)*ld + 2*(n0+g)];
    bh[0]=fu(v0.x); bl[0]=fu(v0.y);
    bh[1]=fu(v1.x); bl[1]=fu(v1.y);
}
__device__ __forceinline__ void ldBfT_p(const float* S, int ld, int k0, int n0, int lane,
                                        uint32_t* bh, uint32_t* bl){
    int g = lane >> 2, tg = lane & 3;
    float2 v0 = *(const float2*)&S[(n0+g)*ld + 2*(k0+tg)];
    float2 v1 = *(const float2*)&S[(n0+g)*ld + 2*(k0+tg+4)];
    bh[0]=fu(v0.x); bl[0]=fu(v0.y);
    bh[1]=fu(v1.x); bl[1]=fu(v1.y);
}

// ---------------- cluster helpers -----------------
#define CLUSTER_SYNC() do{ \
    asm volatile("barrier.cluster.arrive.aligned;" ::: "memory"); \
    asm volatile("barrier.cluster.wait.aligned;"   ::: "memory"); }while(0)

__device__ __forceinline__ uint32_t mapa_u32(uint32_t laddr, uint32_t rank){
    uint32_t ra; asm("mapa.shared::cluster.u32 %0, %1, %2;" : "=r"(ra) : "r"(laddr), "r"(rank));
    return ra;
}
__device__ __forceinline__ float4 peer_f4(uint32_t laddr, uint32_t peer){
    uint32_t ra = mapa_u32(laddr, peer);
    float4 v;
    asm volatile("ld.shared::cluster.v4.f32 {%0,%1,%2,%3}, [%4];"
        : "=f"(v.x),"=f"(v.y),"=f"(v.z),"=f"(v.w) : "r"(ra));
    return v;
}
__device__ __forceinline__ float2 peer_f2(uint32_t laddr, uint32_t peer){
    uint32_t ra = mapa_u32(laddr, peer);
    float2 v;
    asm volatile("ld.shared::cluster.v2.f32 {%0,%1}, [%2];"
        : "=f"(v.x),"=f"(v.y) : "r"(ra));
    return v;
}
__device__ __forceinline__ float peer_f1(uint32_t laddr, uint32_t peer){
    uint32_t ra = mapa_u32(laddr, peer);
    float v;
    asm volatile("ld.shared::cluster.f32 %0, [%1];" : "=f"(v) : "r"(ra));
    return v;
}

// ---------------- prep kernels -----------------
__global__ void __launch_bounds__(256) round_kernel(const float* __restrict__ in,
                                                    float* __restrict__ out){
    size_t i = (size_t)blockIdx.x*256 + threadIdx.x;
    float4 v = ((const float4*)in)[i];
    ((float4*)out)[i] = make_float4(to_tf32(v.x), to_tf32(v.y), to_tf32(v.z), to_tf32(v.w));
}
// fused 3-way transpose (z selects source)
__global__ void __launch_bounds__(256) transpose3_kernel(const float* __restrict__ Wq,
                                                         const float* __restrict__ Wk,
                                                         const float* __restrict__ Wv,
                                                         float* __restrict__ out){
    __shared__ float tile[32][33];
    const float* in = (blockIdx.z==0) ? Wq : (blockIdx.z==1) ? Wk : Wv;
    float* o = out + (size_t)blockIdx.z*CC*CC;
    int bx = blockIdx.x*32, by = blockIdx.y*32;
    int tx = threadIdx.x & 31, ty = threadIdx.x >> 5;
    for (int r = ty; r < 32; r += 8)
        tile[r][tx] = in[(size_t)(by+r)*CC + bx + tx];
    __syncthreads();
    for (int r = ty; r < 32; r += 8)
        o[(size_t)(bx+r)*CC + by + tx] = to_tf32(tile[tx][r]);
}
__global__ void __launch_bounds__(256) transpose_kernel(const float* __restrict__ in,
                                                        float* __restrict__ out){
    __shared__ float tile[32][33];
    int bx = blockIdx.x*32, by = blockIdx.y*32;
    int tx = threadIdx.x & 31, ty = threadIdx.x >> 5;
    for (int r = ty; r < 32; r += 8)
        tile[r][tx] = in[(size_t)(by+r)*CC + bx + tx];
    __syncthreads();
    for (int r = ty; r < 32; r += 8)
        out[(size_t)(bx+r)*CC + by + tx] = to_tf32(tile[tx][r]);
}

// ---------------- tf32 GEMM (R8 core, fused-QKV epilogue) --------------------
#define GPAD 36
template<int SPLIT>
__global__ void __launch_bounds__(256) gemm_tf32(const float* __restrict__ A,
                                                 const float* __restrict__ BT,
                                                 float* __restrict__ out)
{
    __shared__ float As[128*GPAD];
    __shared__ float Bs[128*GPAD];
    const int t = threadIdx.x, lane = t & 31, warp = t >> 5;
    const int wm = warp >> 1, wn = warp & 1;
    const int bm = blockIdx.y, bn = blockIdx.x;

    float acc[2][8][4];
#pragma unroll
    for (int i=0;i<2;i++)
#pragma unroll
        for (int j=0;j<8;j++)
#pragma unroll
            for (int q=0;q<4;q++) acc[i][j][q]=0.f;

    const uint32_t As_u = (uint32_t)__cvta_generic_to_shared(As);
    const uint32_t Bs_u = (uint32_t)__cvta_generic_to_shared(Bs);
    uint32_t a_addr[2], b_addr[4];
#pragma unroll
    for (int mf=0; mf<2; mf++){
        int row = wm*32 + mf*16 + (lane & 15);
        a_addr[mf] = As_u + (uint32_t)(row*GPAD + (lane>>4)*4)*4u;
    }
#pragma unroll
    for (int nf2=0; nf2<4; nf2++){
        int nr = wn*64 + nf2*16 + (lane & 7) + ((lane>>4)&1)*8;
        b_addr[nf2] = Bs_u + (uint32_t)(nr*GPAD + ((lane>>3)&1)*4)*4u;
    }

    const float* Ab  = A  + (size_t)(bm*128)*CC;
    const float* BTb = BT + (size_t)(bn*128)*CC;
    const int row = t >> 3, k4 = (t & 7)*4;

    float4 ar[4], br[4];
#pragma unroll
    for (int i=0;i<4;i++){
        int r = row + i*32;
        ar[i] = *(const float4*)(Ab  + (size_t)r*CC + k4);
        br[i] = *(const float4*)(BTb + (size_t)r*CC + k4);
    }

    for (int it=0; it<32; it++){
        __syncthreads();
#pragma unroll
        for (int i=0;i<4;i++){
            int r = row + i*32;
            *(float4*)&As[r*GPAD + k4] = ar[i];
            *(float4*)&Bs[r*GPAD + k4] = br[i];
        }
        __syncthreads();
        if (it < 31){
            const int kb = (it+1)*32;
#pragma unroll
            for (int i=0;i<4;i++){
                int r = row + i*32;
                ar[i] = *(const float4*)(Ab  + (size_t)r*CC + kb + k4);
                br[i] = *(const float4*)(BTb + (size_t)r*CC + kb + k4);
            }
        }
#pragma unroll
        for (int s8=0; s8<4; s8++){
            uint32_t a[2][4], bf[4][4];
            ldsm4(a[0], a_addr[0] + s8*32);
            ldsm4(a[1], a_addr[1] + s8*32);
            ldsm4(bf[0], b_addr[0] + s8*32);
            ldsm4(bf[1], b_addr[1] + s8*32);
            ldsm4(bf[2], b_addr[2] + s8*32);
            ldsm4(bf[3], b_addr[3] + s8*32);
#pragma unroll
            for (int nf=0; nf<8; nf++){
                uint32_t b0 = bf[nf>>1][(nf&1)*2], b1 = bf[nf>>1][(nf&1)*2+1];
                mma_tf32(acc[0][nf], a[0], b0, b1);
                mma_tf32(acc[1][nf], a[1], b0, b1);
            }
        }
    }

#pragma unroll
    for (int mf=0; mf<2; mf++){
#pragma unroll
        for (int nf=0; nf<8; nf++){
            int r = bm*128 + wm*32 + mf*16 + (lane>>2);
            int c = bn*128 + wn*64 + nf*8 + (lane&3)*2;
#pragma unroll
            for (int half=0; half<2; half++){
                int rr = r + half*8;
                float2 v = make_float2(acc[mf][nf][half*2], acc[mf][nf][half*2+1]);
                if (SPLIT){
                    int proj = c >> 10, cc = c & 1023;
                    int b = rr >> 12, l = rr & 4095;
                    int n = l >> 4, s = l & 15;
                    int h = cc >> 6, f = cc & 63;
                    size_t idx = (size_t)proj*XSZ +
                                 ((((size_t)(b*NHH + h)*NCC + n)*CSS + s)*HFF + f);
                    *(float2*)(out + idx) = v;
                } else {
                    *(float2*)(out + (size_t)rr*CC + c) = v;
                }
            }
        }
    }
}

// ---------------- ilr / coeff -----------------
__global__ void __launch_bounds__(256) ilr_kernel(const float* __restrict__ hs,
                                                  const float* __restrict__ ilw,
                                                  const float* __restrict__ ilb)
{
    const int h = threadIdx.x, rloc = threadIdx.y;
    const int row = blockIdx.x*16 + rloc;
    const float* hp = hs + (size_t)row*CC;
    float a0=0.f,a1=0.f,a2=0.f,a3=0.f;
    for (int k=0;k<CC;k+=4){
        float4 x = *(const float4*)(hp + k);
        a0 += x.x*ilw[(k+0)*NHH+h];
        a1 += x.y*ilw[(k+1)*NHH+h];
        a2 += x.z*ilw[(k+2)*NHH+h];
        a3 += x.w*ilw[(k+3)*NHH+h];
    }
    float acc = (a0+a1)+(a2+a3) + ilb[h];
    float sig = 1.f/(1.f+expf(-acc));
    int b = row>>12, l = row&4095, n = l>>4, s = l&15;
    g_coef[((size_t)(b*NHH+h)*NCC+n)*CSS+s] = sig*(1.f/(float)(s+1))*(1.f/(float)HFF);
}

// ---------------- TTT scan: 2-CTA cluster per head, pre-split operands -------
#define PW2 136   // W2 pair row (2*64+8)
#define PXP 136   // XB/XC pair row
#define PZP 264   // Z1/Z1b/G1 pair row (2*128+8)
#define PGP 136   // G2 pair row
#define PAP 40    // A1m/A2m pair row (2*16+8)

#define C_W1    0                        // raw 64x132
#define C_W2P   (C_W1 + 64*132)          // 128x136 pairs
#define C_XA    (C_W2P + 128*PW2)        // raw 16x68
#define C_XBP   (C_XA + 16*68)           // 16x136 pairs
#define C_XCP   (C_XBP + 16*PXP)
#define C_Z1P   (C_XCP + 16*PXP)         // 16x264 pairs
#define C_Z1BP  (C_Z1P + 16*PZP)
#define C_G1P   (C_Z1BP + 16*PZP)
#define C_G2P   (C_G1P + 16*PZP)         // 16x136 pairs
#define C_A1MP  (C_G2P + 16*PGP)         // 16x40 pairs
#define C_A2MP  (C_A1MP + 16*PAP)
#define C_Z2R   (C_A2MP + 16*PAP)        // raw 16x72 (DSMEM)
#define C_Z2BR  (C_Z2R + 16*72)          // raw 16x72 (DSMEM)
#define C_A2PR  (C_Z2BR + 16*72)         // raw 16x20 (DSMEM)
#define C_ST    (C_A2PR + 16*20)         // 8x16x18 staging
#define C_CO    (C_ST + 8*16*18)         // 16
#define SCAN_SMEM_FLOATS (C_CO + 16)
#define SCAN_SMEM_BYTES  (SCAN_SMEM_FLOATS*4)

__global__ void __launch_bounds__(256,1) __cluster_dims__(2,1,1)
scan_kernel(const float* __restrict__ W1g, const float* __restrict__ W2g)
{
    extern __shared__ float sm[];
    float* sW1  = sm + C_W1;
    float* sW2p = sm + C_W2P;
    float* sXA  = sm + C_XA;
    float* sXBp = sm + C_XBP;
    float* sXCp = sm + C_XCP;
    float* sZ1p = sm + C_Z1P;
    float* sZ1bp= sm + C_Z1BP;
    float* sG1p = sm + C_G1P;
    float* sG2p = sm + C_G2P;
    float* sA1mp= sm + C_A1MP;
    float* sA2mp= sm + C_A2MP;
    float* sZ2r = sm + C_Z2R;
    float* sZ2br= sm + C_Z2BR;
    float* sA2pr= sm + C_A2PR;
    float* sSt  = sm + C_ST;
    float* sCo  = sm + C_CO;

    const int t = threadIdx.x;
    const int lane = t & 31, w = t >> 5;
    const int g = lane >> 2, tg = lane & 3;
    uint32_t rank; asm("mov.u32 %0, %%cluster_ctarank;" : "=r"(rank));
    const uint32_t peer = rank ^ 1u;
    const int bh = blockIdx.x >> 1;
    const int b  = bh >> 4, h = bh & 15;
    const uint32_t smb = (uint32_t)__cvta_generic_to_shared(sm);

    // initial state: W1 raw local slice; W2 pair local slice
    const float* w1p = W1g + (size_t)h*HFF*HF4;
    for (int i = t; i < HFF*128; i += 256)
        sW1[(i>>7)*132 + (i&127)] = w1p[(size_t)(i>>7)*HF4 + rank*128 + (i&127)];
    const float* w2p = W2g + (size_t)h*HF4*HFF;
    for (int i = t; i < 128*HFF; i += 256){
        int k = i>>6, f = i&63;
        *(float2*)&sW2p[k*PW2 + 2*f] = sp(w2p[(size_t)(rank*128 + k)*HFF + f]);
    }

    const size_t cbase = (size_t)bh * (NCC*CSS*HFF);
    const float* gXC = g_X;
    const float* gXB = g_X + XSZ;
    const float* gXA = g_X + 2*(size_t)XSZ;

    for (int n = 0; n < NCC; n++) {
        // ---- chunk load: XA raw; XB/XC split pairs ----
        {
            const float4* xa4 = (const float4*)(gXA + cbase + (size_t)n*1024);
            const float4* xb4 = (const float4*)(gXB + cbase + (size_t)n*1024);
            const float4* xc4 = (const float4*)(gXC + cbase + (size_t)n*1024);
            int e = t*4, s = e >> 6, f = e & 63;
            float4 va = xa4[t], vb = xb4[t], vc = xc4[t];
            *(float4*)(sXA + s*68 + f) = va;
            float2 b0=sp(vb.x), b1=sp(vb.y), b2=sp(vb.z), b3=sp(vb.w);
            *(float4*)&sXBp[s*PXP + 2*f]     = make_float4(b0.x,b0.y,b1.x,b1.y);
            *(float4*)&sXBp[s*PXP + 2*f + 4] = make_float4(b2.x,b2.y,b3.x,b3.y);
            float2 c0=sp(vc.x), c1_=sp(vc.y), c2=sp(vc.z), c3=sp(vc.w);
            *(float4*)&sXCp[s*PXP + 2*f]     = make_float4(c0.x,c0.y,c1_.x,c1_.y);
            *(float4*)&sXCp[s*PXP + 2*f + 4] = make_float4(c2.x,c2.y,c3.x,c3.y);
            if (t < 16) sCo[t] = g_coef[(size_t)bh*(NCC*CSS) + n*CSS + t];
        }
        __syncthreads();

        // ---- P1: Z1loc = XB@W1loc ; Ploc = XC@W1loc -> split pairs ----
        {
            const int n0 = w*16;
            float aZ[2][4], aP[2][4];
#pragma unroll
            for (int i=0;i<2;i++)
#pragma unroll
                for (int q=0;q<4;q++){ aZ[i][q]=0.f; aP[i][q]=0.f; }
#pragma unroll
            for (int ks=0; ks<8; ks++){
                int k0 = ks*8;
                uint32_t aBh[4],aBl[4],aCh[4],aCl[4];
                ldAf_p(sXBp, PXP, k0, lane, aBh, aBl);
                ldAf_p(sXCp, PXP, k0, lane, aCh, aCl);
#pragma unroll
                for (int nf=0; nf<2; nf++){
                    uint32_t bhf[2], blf[2];
                    ldBf(sW1, 132, k0, n0+nf*8, lane, bhf, blf);
                    mma3(aZ[nf], aBh, aBl, bhf, blf);
                    mma3(aP[nf], aCh, aCl, bhf, blf);
                }
            }
#pragma unroll
            for (int nf=0; nf<2; nf++){
                int col = n0 + nf*8 + 2*tg;
                float2 z0=sp(aZ[nf][0]), z1=sp(aZ[nf][1]), z2=sp(aZ[nf][2]), z3=sp(aZ[nf][3]);
                *(float4*)&sZ1p[g*PZP + 2*col]     = make_float4(z0.x,z0.y,z1.x,z1.y);
                *(float4*)&sZ1p[(g+8)*PZP + 2*col] = make_float4(z2.x,z2.y,z3.x,z3.y);
                float2 p0=sp(aP[nf][0]), p1=sp(aP[nf][1]), p2=sp(aP[nf][2]), p3=sp(aP[nf][3]);
                *(float4*)&sZ1bp[g*PZP + 2*col]     = make_float4(p0.x,p0.y,p1.x,p1.y);
                *(float4*)&sZ1bp[(g+8)*PZP + 2*col] = make_float4(p2.x,p2.y,p3.x,p3.y);
            }
        }
        __syncthreads();

        // ---- P2: Z2 partial ; warps 0,1: A1m pairs ----
        {
            const int n0 = w*8;
            float acc[4] = {0.f,0.f,0.f,0.f};
#pragma unroll 4
            for (int ks=0; ks<16; ks++){
                int k0 = ks*8;
                uint32_t ah[4],al[4],bhf[2],blf[2];
                ldAf_p(sZ1p, PZP, k0, lane, ah, al);
                ldBf_p(sW2p, PW2, k0, n0, lane, bhf, blf);
                mma3(acc, ah, al, bhf, blf);
            }
            {
                int col = n0 + 2*tg;
                *(float2*)&sZ2r[g*72 + col]     = make_float2(acc[0], acc[1]);
                *(float2*)&sZ2r[(g+8)*72 + col] = make_float2(acc[2], acc[3]);
            }
            if (w < 2){
                const int an0 = w*8;
                float a1[4] = {0.f,0.f,0.f,0.f};
#pragma unroll
                for (int ks=0; ks<8; ks++){
                    int k0 = ks*8;
                    uint32_t ah[4],al[4],bhf[2],blf[2];
                    ldAf_p(sXCp, PXP, k0, lane, ah, al);
                    ldBfT_p(sXBp, PXP, k0, an0, lane, bhf, blf);
                    mma3(a1, ah, al, bhf, blf);
                }
                int u0 = an0 + 2*tg;
                int s0 = g, s1 = g+8;
                float2 zz = make_float2(0.f,0.f);
                *(float2*)&sA1mp[s0*PAP + 2*u0]     = (u0   <= s0) ? sp(-sCo[s0]*a1[0]) : zz;
                *(float2*)&sA1mp[s0*PAP + 2*(u0+1)] = (u0+1 <= s0) ? sp(-sCo[s0]*a1[1]) : zz;
                *(float2*)&sA1mp[s1*PAP + 2*u0]     = (u0   <= s1) ? sp(-sCo[s1]*a1[2]) : zz;
                *(float2*)&sA1mp[s1*PAP + 2*(u0+1)] = (u0+1 <= s1) ? sp(-sCo[s1]*a1[3]) : zz;
            }
        }
        CLUSTER_SYNC();

        // ---- g2 = Z2_own + Z2_peer - XA -> split pairs ----
        {
            int row = t >> 4, c4 = (t & 15)*4;
            float4 own = *(float4*)&sZ2r[row*72 + c4];
            float4 pv  = peer_f4(smb + (uint32_t)(C_Z2R + row*72 + c4)*4u, peer);
            float4 xa  = *(float4*)&sXA[row*68 + c4];
            float2 g0 = sp(own.x+pv.x-xa.x), g1_ = sp(own.y+pv.y-xa.y);
            float2 g2_ = sp(own.z+pv.z-xa.z), g3 = sp(own.w+pv.w-xa.w);
            *(float4*)&sG2p[row*PGP + 2*c4]     = make_float4(g0.x,g0.y,g1_.x,g1_.y);
            *(float4*)&sG2p[row*PGP + 2*c4 + 4] = make_float4(g2_.x,g2_.y,g3.x,g3.y);
        }
        __syncthreads();

        // ---- P3: g1loc = g2 @ W2loc^T -> split pairs ----
        {
            const int n0 = w*16;
            float accG[2][4];
#pragma unroll
            for (int i=0;i<2;i++)
#pragma unroll
                for (int q=0;q<4;q++) accG[i][q]=0.f;
#pragma unroll
            for (int ks=0; ks<8; ks++){
                int k0 = ks*8;
                uint32_t ah[4],al[4];
                ldAf_p(sG2p, PGP, k0, lane, ah, al);
#pragma unroll
                for (int nf=0; nf<2; nf++){
                    uint32_t bhf[2], blf[2];
                    ldBfT_p(sW2p, PW2, k0, n0+nf*8, lane, bhf, blf);
                    mma3(accG[nf], ah, al, bhf, blf);
                }
            }
#pragma unroll
            for (int nf=0; nf<2; nf++){
                int col = n0 + nf*8 + 2*tg;
                float2 q0=sp(accG[nf][0]), q1=sp(accG[nf][1]), q2=sp(accG[nf][2]), q3=sp(accG[nf][3]);
                *(float4*)&sG1p[g*PZP + 2*col]     = make_float4(q0.x,q0.y,q1.x,q1.y);
                *(float4*)&sG1p[(g+8)*PZP + 2*col] = make_float4(q2.x,q2.y,q3.x,q3.y);
            }
        }
        __syncthreads();

        // ---- P4: Z1b += A1m@g1loc (pair update) ; W1 -= cl*(XB^T@g1loc) ----
        {
            const int n0 = w*16;
            float c1[2][4];
#pragma unroll
            for (int i=0;i<2;i++)
#pragma unroll
                for (int q=0;q<4;q++) c1[i][q]=0.f;
#pragma unroll
            for (int ks=0; ks<2; ks++){
                int k0 = ks*8;
                uint32_t ah[4],al[4];
                ldAf_p(sA1mp, PAP, k0, lane, ah, al);
#pragma unroll
                for (int nf=0; nf<2; nf++){
                    uint32_t bhf[2], blf[2];
                    ldBf_p(sG1p, PZP, k0, n0+nf*8, lane, bhf, blf);
                    mma3(c1[nf], ah, al, bhf, blf);
                }
            }
#pragma unroll
            for (int nf=0; nf<2; nf++){
                int col = n0 + nf*8 + 2*tg;
                float4 r0 = *(float4*)&sZ1bp[g*PZP + 2*col];
                float4 r1 = *(float4*)&sZ1bp[(g+8)*PZP + 2*col];
                float v00 = r0.x+r0.y + c1[nf][0];
                float v01 = r0.z+r0.w + c1[nf][1];
                float v10 = r1.x+r1.y + c1[nf][2];
                float v11 = r1.z+r1.w + c1[nf][3];
                float2 s00=sp(v00), s01=sp(v01), s10=sp(v10), s11=sp(v11);
                *(float4*)&sZ1bp[g*PZP + 2*col]     = make_float4(s00.x,s00.y,s01.x,s01.y);
                *(float4*)&sZ1bp[(g+8)*PZP + 2*col] = make_float4(s10.x,s10.y,s11.x,s11.y);
            }
            const float cl = sCo[15];
            const int m0 = (w>>1)*16, nbase = (w&1)*64;
            float wa[8][4];
#pragma unroll
            for (int i=0;i<8;i++)
#pragma unroll
                for (int q=0;q<4;q++) wa[i][q]=0.f;
#pragma unroll
            for (int ks=0; ks<2; ks++){
                int k0 = ks*8;
                uint32_t ah[4],al[4];
                ldAfT_p(sXBp, PXP, m0, k0, lane, ah, al);
#pragma unroll
                for (int nf=0; nf<8; nf++){
                    uint32_t bhf[2], blf[2];
                    ldBf_p(sG1p, PZP, k0, nbase + nf*8, lane, bhf, blf);
                    mma3(wa[nf], ah, al, bhf, blf);
                }
            }
#pragma unroll
            for (int nf=0; nf<8; nf++){
                int col = nbase + nf*8 + 2*tg;
                float2 v0 = *(float2*)&sW1[(m0+g)*132 + col];
                float2 v1 = *(float2*)&sW1[(m0+g+8)*132 + col];
                v0.x -= cl*wa[nf][0]; v0.y -= cl*wa[nf][1];
                v1.x -= cl*wa[nf][2]; v1.y -= cl*wa[nf][3];
                *(float2*)&sW1[(m0+g)*132 + col]   = v0;
                *(float2*)&sW1[(m0+g+8)*132 + col] = v1;
            }
        }
        __syncthreads();

        // ---- P5: Z2b partial ; A2 partial ----
        float zacc[4] = {0.f,0.f,0.f,0.f};
        {
            const int n0 = w*8;
#pragma unroll 4
            for (int ks=0; ks<16; ks++){
                int k0 = ks*8;
                uint32_t ah[4],al[4],bhf[2],blf[2];
                ldAf_p(sZ1bp, PZP, k0, lane, ah, al);
                ldBf_p(sW2p, PW2, k0, n0, lane, bhf, blf);
                mma3(zacc, ah, al, bhf, blf);
            }
            {
                int col = n0 + 2*tg;
                *(float2*)&sZ2br[g*72 + col]     = make_float2(zacc[0], zacc[1]);
                *(float2*)&sZ2br[(g+8)*72 + col] = make_float2(zacc[2], zacc[3]);
            }
            float pa[2][4];
#pragma unroll
            for (int i=0;i<2;i++)
#pragma unroll
                for (int q=0;q<4;q++) pa[i][q]=0.f;
            const int kb = w*16;
#pragma unroll
            for (int ks=0; ks<2; ks++){
                int k0 = kb + ks*8;
                uint32_t ah[4],al[4];
                ldAf_p(sZ1bp, PZP, k0, lane, ah, al);
#pragma unroll
                for (int nf=0; nf<2; nf++){
                    uint32_t bhf[2], blf[2];
                    ldBfT_p(sZ1p, PZP, k0, nf*8, lane, bhf, blf);
                    mma3(pa[nf], ah, al, bhf, blf);
                }
            }
#pragma unroll
            for (int nf=0; nf<2; nf++){
                int u = nf*8 + 2*tg;
                sSt[w*288 + g*18 + u]       = pa[nf][0];
                sSt[w*288 + g*18 + u+1]     = pa[nf][1];
                sSt[w*288 + (g+8)*18 + u]   = pa[nf][2];
                sSt[w*288 + (g+8)*18 + u+1] = pa[nf][3];
            }
        }
        __syncthreads();

        // ---- P5r: reduce staged A2 partials -> CTA partial (raw) ----
        {
            int s = t >> 4, u = t & 15;
            float sum = 0.f;
#pragma unroll
            for (int ww=0; ww<8; ww++) sum += sSt[ww*288 + s*18 + u];
            sA2pr[s*20 + u] = sum;
        }
        CLUSTER_SYNC();

        // ---- A2m pairs = split(-co*tril(A2_own + A2_peer)) ----
        {
            int s = t >> 4, u = t & 15;
            float pv = peer_f1(smb + (uint32_t)(C_A2PR + s*20 + u)*4u, peer);
            float sum = sA2pr[s*20 + u] + pv;
            *(float2*)&sA2mp[s*PAP + 2*u] =
                (u <= s) ? sp(-sCo[s]*sum) : make_float2(0.f,0.f);
        }
        __syncthreads();

        // ---- P6: corr2 ; combine + store ; W2 pair update ----
        {
            const int n0 = w*8;
#pragma unroll
            for (int ks=0; ks<2; ks++){
                int k0 = ks*8;
                uint32_t ah[4],al[4],bhf[2],blf[2];
                ldAf_p(sA2mp, PAP, k0, lane, ah, al);
                ldBf_p(sG2p, PGP, k0, n0, lane, bhf, blf);
                mma3(zacc, ah, al, bhf, blf);
            }
            {
                int srow = rank ? (g+8) : g;
                float2 pv = peer_f2(smb + (uint32_t)(C_Z2BR + srow*72 + n0 + 2*tg)*4u, peer);
                float2 ownv = rank ? make_float2(zacc[2], zacc[3])
                                   : make_float2(zacc[0], zacc[1]);
                int col = h*HFF + n0 + 2*tg;
                size_t ridx = (size_t)(b*LL + n*CSS + srow)*CC + col;
                *(float2*)&g_Z2b[ridx] =
                    make_float2(to_tf32(ownv.x + pv.x), to_tf32(ownv.y + pv.y));
            }
            const float cl = sCo[15];
            const int m0 = w*16;
            float wa[8][4];
#pragma unroll
            for (int i=0;i<8;i++)
#pragma unroll
                for (int q=0;q<4;q++) wa[i][q]=0.f;
#pragma unroll
            for (int ks=0; ks<2; ks++){
                int k0 = ks*8;
                uint32_t ah[4],al[4];
                ldAfT_p(sZ1p, PZP, m0, k0, lane, ah, al);
#pragma unroll
                for (int nf=0; nf<8; nf++){
                    uint32_t bhf[2], blf[2];
                    ldBf_p(sG2p, PGP, k0, nf*8, lane, bhf, blf);
                    mma3(wa[nf], ah, al, bhf, blf);
                }
            }
#pragma unroll
            for (int nf=0; nf<8; nf++){
                int col = nf*8 + 2*tg;
                float4 r0 = *(float4*)&sW2p[(m0+g)*PW2 + 2*col];
                float4 r1 = *(float4*)&sW2p[(m0+g+8)*PW2 + 2*col];
                float va = r0.x+r0.y - cl*wa[nf][0];
                float vb = r0.z+r0.w - cl*wa[nf][1];
                float vc = r1.x+r1.y - cl*wa[nf][2];
                float vd = r1.z+r1.w - cl*wa[nf][3];
                float2 sa=sp(va), sb=sp(vb), sc=sp(vc), sd=sp(vd);
                *(float4*)&sW2p[(m0+g)*PW2 + 2*col]   = make_float4(sa.x,sa.y,sb.x,sb.y);
                *(float4*)&sW2p[(m0+g+8)*PW2 + 2*col] = make_float4(sc.x,sc.y,sd.x,sd.y);
            }
        }
        __syncthreads();
    }
    CLUSTER_SYNC();
}

// ---------------- launch -----------------
extern "C" void kernel_launch(void* const* d_in, const int* in_sizes, int n_in,
                              void* d_out, int out_size)
{
    const float* hs  = (const float*)d_in[0];
    const float* Wq  = (const float*)d_in[1];
    const float* Wk  = (const float*)d_in[2];
    const float* Wv  = (const float*)d_in[3];
    const float* Wo  = (const float*)d_in[4];
    const float* ilw = (const float*)d_in[5];
    const float* ilb = (const float*)d_in[6];
    const float* W1  = (const float*)d_in[7];
    const float* W2  = (const float*)d_in[8];
    float* out = (float*)d_out;

    cudaFuncSetAttribute(scan_kernel, cudaFuncAttributeMaxDynamicSharedMemorySize,
                         SCAN_SMEM_BYTES);

    void *pX, *pZ2b, *pHsr, *pWT;
    cudaGetSymbolAddress(&pX, g_X);
    cudaGetSymbolAddress(&pZ2b, g_Z2b);
    cudaGetSymbolAddress(&pHsr, g_hsr);
    cudaGetSymbolAddress(&pWT, g_WT);
    float* hsr = (float*)pHsr;
    float* WT  = (float*)pWT;

    // launch 1-3
    round_kernel<<<(size_t)MROWS*CC/4/256, 256>>>(hs, hsr);
    transpose3_kernel<<<dim3(32,32,3), 256>>>(Wq, Wk, Wv, WT);
    ilr_kernel<<<MROWS/16, dim3(16,16)>>>(hs, ilw, ilb);

    // launch 4: fused QKV GEMM (ncu capture slot = my 4th launch)
    dim3 gq(3*CC/128, MROWS/128);
    gemm_tf32<1><<<gq, 256>>>(hsr, WT, (float*)pX);

    // launch 5-7
    scan_kernel<<<BB*NHH*2, 256, SCAN_SMEM_BYTES>>>(W1, W2);
    transpose_kernel<<<dim3(32,32), 256>>>(Wo, WT + 3*(size_t)CC*CC);
    dim3 go(CC/128, MROWS/128);
    gemm_tf32<0><<<go, 256>>>((const float*)pZ2b, WT + 3*(size_t)CC*CC, out);
}

// round 12
// speedup vs baseline: 1.0207x; 1.0207x over previous
#include <cuda_runtime.h>
#include <math.h>
#include <stdint.h>

#define BB 4
#define LL 4096
#define CC 1024
#define NHH 16
#define CSS 16
#define HFF 64
#define HF4 256
#define NCC 256
#define MROWS (BB*LL)   // 16384
#define XSZ (BB*NHH*NCC*CSS*HFF)

// ---------------- device scratch -----------------
__device__ float g_X[3*XSZ];                 // [0]=XC, [1]=XB, [2]=XA (split layout)
__device__ float g_coef[BB*NHH*NCC*CSS];
__device__ float g_Z2b[(size_t)MROWS*CC];
__device__ float g_hsr[(size_t)MROWS*CC];
__device__ float g_WT[4][CC*CC];

// ---------------- helpers -----------------
__device__ __forceinline__ float to_tf32(float x){
    uint32_t u; asm("cvt.rna.tf32.f32 %0, %1;" : "=r"(u) : "f"(x));
    return __uint_as_float(u);
}
__device__ __forceinline__ uint32_t f2tf(float x){
    uint32_t u; asm("cvt.rna.tf32.f32 %0, %1;" : "=r"(u) : "f"(x));
    return u;
}
__device__ __forceinline__ void splitf(float v, uint32_t& h, uint32_t& l){
    h = f2tf(v);
    l = f2tf(v - __uint_as_float(h));
}
__device__ __forceinline__ void ldsm4(uint32_t* r, uint32_t addr){
    asm volatile("ldmatrix.sync.aligned.m8n8.x4.shared.b16 {%0,%1,%2,%3}, [%4];"
        : "=r"(r[0]),"=r"(r[1]),"=r"(r[2]),"=r"(r[3]) : "r"(addr));
}
__device__ __forceinline__ void mma_tf32(float* c, const uint32_t* a, uint32_t b0, uint32_t b1){
    asm volatile("mma.sync.aligned.m16n8k8.row.col.f32.tf32.tf32.f32 "
        "{%0,%1,%2,%3},{%4,%5,%6,%7},{%8,%9},{%0,%1,%2,%3};"
        : "+f"(c[0]),"+f"(c[1]),"+f"(c[2]),"+f"(c[3])
        : "r"(a[0]),"r"(a[1]),"r"(a[2]),"r"(a[3]),"r"(b0),"r"(b1));
}
__device__ __forceinline__ void mma3(float* c, const uint32_t* ah, const uint32_t* al,
                                     const uint32_t* bh, const uint32_t* bl){
    mma_tf32(c, ah, bh[0], bh[1]);
    mma_tf32(c, ah, bl[0], bl[1]);
    mma_tf32(c, al, bh[0], bh[1]);
}
__device__ __forceinline__ void ldAf(const float* S, int ld, int k0, int lane,
                                     uint32_t* ah, uint32_t* al, float scale){
    int g = lane >> 2, tg = lane & 3;
    float v0 = S[g*ld + k0+tg]       * scale;
    float v1 = S[(g+8)*ld + k0+tg]   * scale;
    float v2 = S[g*ld + k0+tg+4]     * scale;
    float v3 = S[(g+8)*ld + k0+tg+4] * scale;
    splitf(v0, ah[0], al[0]); splitf(v1, ah[1], al[1]);
    splitf(v2, ah[2], al[2]); splitf(v3, ah[3], al[3]);
}
__device__ __forceinline__ void ldAfT(const float* S, int ld, int m0, int k0, int lane,
                                      uint32_t* ah, uint32_t* al, float scale){
    int g = lane >> 2, tg = lane & 3;
    float v0 = S[(k0+tg)*ld + m0+g]     * scale;
    float v1 = S[(k0+tg)*ld + m0+g+8]   * scale;
    float v2 = S[(k0+tg+4)*ld + m0+g]   * scale;
    float v3 = S[(k0+tg+4)*ld + m0+g+8] * scale;
    splitf(v0, ah[0], al[0]); splitf(v1, ah[1], al[1]);
    splitf(v2, ah[2], al[2]); splitf(v3, ah[3], al[3]);
}
__device__ __forceinline__ void ldBf(const float* S, int ld, int k0, int n0, int lane,
                                     uint32_t* bh, uint32_t* bl){
    int g = lane >> 2, tg = lane & 3;
    splitf(S[(k0+tg)*ld + n0+g],   bh[0], bl[0]);
    splitf(S[(k0+tg+4)*ld + n0+g], bh[1], bl[1]);
}
__device__ __forceinline__ void ldBfT(const float* S, int ld, int k0, int n0, int lane,
                                      uint32_t* bh, uint32_t* bl){
    int g = lane >> 2, tg = lane & 3;
    splitf(S[(n0+g)*ld + k0+tg],   bh[0], bl[0]);
    splitf(S[(n0+g)*ld + k0+tg+4], bh[1], bl[1]);
}

// ---------------- cluster helpers -----------------
#define CLUSTER_SYNC() do{ \
    asm volatile("barrier.cluster.arrive.aligned;" ::: "memory"); \
    asm volatile("barrier.cluster.wait.aligned;"   ::: "memory"); }while(0)

__device__ __forceinline__ uint32_t mapa_u32(uint32_t laddr, uint32_t rank){
    uint32_t ra; asm("mapa.shared::cluster.u32 %0, %1, %2;" : "=r"(ra) : "r"(laddr), "r"(rank));
    return ra;
}
__device__ __forceinline__ float4 peer_f4(uint32_t laddr, uint32_t peer){
    uint32_t ra = mapa_u32(laddr, peer);
    float4 v;
    asm volatile("ld.shared::cluster.v4.f32 {%0,%1,%2,%3}, [%4];"
        : "=f"(v.x),"=f"(v.y),"=f"(v.z),"=f"(v.w) : "r"(ra));
    return v;
}
__device__ __forceinline__ float2 peer_f2(uint32_t laddr, uint32_t peer){
    uint32_t ra = mapa_u32(laddr, peer);
    float2 v;
    asm volatile("ld.shared::cluster.v2.f32 {%0,%1}, [%2];"
        : "=f"(v.x),"=f"(v.y) : "r"(ra));
    return v;
}
__device__ __forceinline__ float peer_f1(uint32_t laddr, uint32_t peer){
    uint32_t ra = mapa_u32(laddr, peer);
    float v;
    asm volatile("ld.shared::cluster.f32 %0, [%1];" : "=f"(v) : "r"(ra));
    return v;
}

// ---------------- prep kernels -----------------
__global__ void __launch_bounds__(256) round_kernel(const float* __restrict__ in,
                                                    float* __restrict__ out){
    size_t i = (size_t)blockIdx.x*256 + threadIdx.x;
    float4 v = ((const float4*)in)[i];
    ((float4*)out)[i] = make_float4(to_tf32(v.x), to_tf32(v.y), to_tf32(v.z), to_tf32(v.w));
}
// fused: z in [0,3) -> transpose Wq/Wk/Wv ; z==3 -> ilr/coef
__global__ void __launch_bounds__(256) transpose3i_kernel(const float* __restrict__ Wq,
                                                          const float* __restrict__ Wk,
                                                          const float* __restrict__ Wv,
                                                          float* __restrict__ out,
                                                          const float* __restrict__ hs,
                                                          const float* __restrict__ ilw,
                                                          const float* __restrict__ ilb){
    if (blockIdx.z < 3){
        __shared__ float tile[32][33];
        const float* in = (blockIdx.z==0) ? Wq : (blockIdx.z==1) ? Wk : Wv;
        float* o = out + (size_t)blockIdx.z*CC*CC;
        int bx = blockIdx.x*32, by = blockIdx.y*32;
        int tx = threadIdx.x & 31, ty = threadIdx.x >> 5;
        for (int r = ty; r < 32; r += 8)
            tile[r][tx] = in[(size_t)(by+r)*CC + bx + tx];
        __syncthreads();
        for (int r = ty; r < 32; r += 8)
            o[(size_t)(bx+r)*CC + by + tx] = to_tf32(tile[tx][r]);
    } else {
        // ilr: block index = by*32+bx in [0,1024), 16 rows x 16 heads
        int blk = blockIdx.y*32 + blockIdx.x;
        int h = threadIdx.x & 15, rloc = threadIdx.x >> 4;
        int row = blk*16 + rloc;
        const float* hp = hs + (size_t)row*CC;
        float a0=0.f,a1=0.f,a2=0.f,a3=0.f;
        for (int k=0;k<CC;k+=4){
            float4 x = *(const float4*)(hp + k);
            a0 += x.x*ilw[(k+0)*NHH+h];
            a1 += x.y*ilw[(k+1)*NHH+h];
            a2 += x.z*ilw[(k+2)*NHH+h];
            a3 += x.w*ilw[(k+3)*NHH+h];
        }
        float acc = (a0+a1)+(a2+a3) + ilb[h];
        float sig = 1.f/(1.f+expf(-acc));
        int b = row>>12, l = row&4095, n = l>>4, s = l&15;
        g_coef[((size_t)(b*NHH+h)*NCC+n)*CSS+s] = sig*(1.f/(float)(s+1))*(1.f/(float)HFF);
    }
}
__global__ void __launch_bounds__(256) transpose_kernel(const float* __restrict__ in,
                                                        float* __restrict__ out){
    __shared__ float tile[32][33];
    int bx = blockIdx.x*32, by = blockIdx.y*32;
    int tx = threadIdx.x & 31, ty = threadIdx.x >> 5;
    for (int r = ty; r < 32; r += 8)
        tile[r][tx] = in[(size_t)(by+r)*CC + bx + tx];
    __syncthreads();
    for (int r = ty; r < 32; r += 8)
        out[(size_t)(bx+r)*CC + by + tx] = to_tf32(tile[tx][r]);
}

// ---------------- tf32 GEMM (R8 core, fused-QKV epilogue) --------------------
#define GPAD 36
template<int SPLIT>
__global__ void __launch_bounds__(256) gemm_tf32(const float* __restrict__ A,
                                                 const float* __restrict__ BT,
                                                 float* __restrict__ out)
{
    __shared__ float As[128*GPAD];
    __shared__ float Bs[128*GPAD];
    const int t = threadIdx.x, lane = t & 31, warp = t >> 5;
    const int wm = warp >> 1, wn = warp & 1;
    const int bm = blockIdx.y, bn = blockIdx.x;

    float acc[2][8][4];
#pragma unroll
    for (int i=0;i<2;i++)
#pragma unroll
        for (int j=0;j<8;j++)
#pragma unroll
            for (int q=0;q<4;q++) acc[i][j][q]=0.f;

    const uint32_t As_u = (uint32_t)__cvta_generic_to_shared(As);
    const uint32_t Bs_u = (uint32_t)__cvta_generic_to_shared(Bs);
    uint32_t a_addr[2], b_addr[4];
#pragma unroll
    for (int mf=0; mf<2; mf++){
        int row = wm*32 + mf*16 + (lane & 15);
        a_addr[mf] = As_u + (uint32_t)(row*GPAD + (lane>>4)*4)*4u;
    }
#pragma unroll
    for (int nf2=0; nf2<4; nf2++){
        int nr = wn*64 + nf2*16 + (lane & 7) + ((lane>>4)&1)*8;
        b_addr[nf2] = Bs_u + (uint32_t)(nr*GPAD + ((lane>>3)&1)*4)*4u;
    }

    const float* Ab  = A  + (size_t)(bm*128)*CC;
    const float* BTb = BT + (size_t)(bn*128)*CC;
    const int row = t >> 3, k4 = (t & 7)*4;

    float4 ar[4], br[4];
#pragma unroll
    for (int i=0;i<4;i++){
        int r = row + i*32;
        ar[i] = *(const float4*)(Ab  + (size_t)r*CC + k4);
        br[i] = *(const float4*)(BTb + (size_t)r*CC + k4);
    }

    for (int it=0; it<32; it++){
        __syncthreads();
#pragma unroll
        for (int i=0;i<4;i++){
            int r = row + i*32;
            *(float4*)&As[r*GPAD + k4] = ar[i];
            *(float4*)&Bs[r*GPAD + k4] = br[i];
        }
        __syncthreads();
        if (it < 31){
            const int kb = (it+1)*32;
#pragma unroll
            for (int i=0;i<4;i++){
                int r = row + i*32;
                ar[i] = *(const float4*)(Ab  + (size_t)r*CC + kb + k4);
                br[i] = *(const float4*)(BTb + (size_t)r*CC + kb + k4);
            }
        }
#pragma unroll
        for (int s8=0; s8<4; s8++){
            uint32_t a[2][4], bf[4][4];
            ldsm4(a[0], a_addr[0] + s8*32);
            ldsm4(a[1], a_addr[1] + s8*32);
            ldsm4(bf[0], b_addr[0] + s8*32);
            ldsm4(bf[1], b_addr[1] + s8*32);
            ldsm4(bf[2], b_addr[2] + s8*32);
            ldsm4(bf[3], b_addr[3] + s8*32);
#pragma unroll
            for (int nf=0; nf<8; nf++){
                uint32_t b0 = bf[nf>>1][(nf&1)*2], b1 = bf[nf>>1][(nf&1)*2+1];
                mma_tf32(acc[0][nf], a[0], b0, b1);
                mma_tf32(acc[1][nf], a[1], b0, b1);
            }
        }
    }

#pragma unroll
    for (int mf=0; mf<2; mf++){
#pragma unroll
        for (int nf=0; nf<8; nf++){
            int r = bm*128 + wm*32 + mf*16 + (lane>>2);
            int c = bn*128 + wn*64 + nf*8 + (lane&3)*2;
#pragma unroll
            for (int half=0; half<2; half++){
                int rr = r + half*8;
                float2 v = make_float2(acc[mf][nf][half*2], acc[mf][nf][half*2+1]);
                if (SPLIT){
                    int proj = c >> 10, cc = c & 1023;
                    int b = rr >> 12, l = rr & 4095;
                    int n = l >> 4, s = l & 15;
                    int h = cc >> 6, f = cc & 63;
                    size_t idx = (size_t)proj*XSZ +
                                 ((((size_t)(b*NHH + h)*NCC + n)*CSS + s)*HFF + f);
                    *(float2*)(out + idx) = v;
                } else {
                    *(float2*)(out + (size_t)rr*CC + c) = v;
                }
            }
        }
    }
}

// ---------------- TTT scan: 2-CTA cluster per head (R10 version) -------------
#define C_W1   0                        // 64 x 132
#define C_W2   (C_W1 + 64*132)          // 128 x 72
#define C_XA   (C_W2 + 128*72)          // 16 x 68
#define C_XB   (C_XA + 16*68)
#define C_XC   (C_XB + 16*68)
#define C_Z1   (C_XC + 16*68)           // 16 x 132
#define C_Z1B  (C_Z1 + 16*132)
#define C_G1   (C_Z1B + 16*132)
#define C_G2   (C_G1 + 16*132)          // 16 x 72
#define C_Z2P  (C_G2 + 16*72)           // 16 x 72
#define C_Z2BP (C_Z2P + 16*72)          // 16 x 72
#define C_A1M  (C_Z2BP + 16*72)         // 16 x 20
#define C_A2P  (C_A1M + 16*20)          // 16 x 20
#define C_A2M  (C_A2P + 16*20)          // 16 x 20
#define C_ST   (C_A2M + 16*20)          // 8 x 16 x 18
#define C_CO   (C_ST + 8*16*18)         // 16
#define SCAN_SMEM_FLOATS (C_CO + 16)
#define SCAN_SMEM_BYTES  (SCAN_SMEM_FLOATS*4)

__global__ void __launch_bounds__(256,1) __cluster_dims__(2,1,1)
scan_kernel(const float* __restrict__ W1g, const float* __restrict__ W2g)
{
    extern __shared__ float sm[];
    float* sW1  = sm + C_W1;
    float* sW2  = sm + C_W2;
    float* sXA  = sm + C_XA;
    float* sXB  = sm + C_XB;
    float* sXC  = sm + C_XC;
    float* sZ1  = sm + C_Z1;
    float* sZ1b = sm + C_Z1B;
    float* sG1  = sm + C_G1;
    float* sG2  = sm + C_G2;
    float* sZ2p = sm + C_Z2P;
    float* sZ2bp= sm + C_Z2BP;
    float* sA1m = sm + C_A1M;
    float* sA2p = sm + C_A2P;
    float* sA2m = sm + C_A2M;
    float* sSt  = sm + C_ST;
    float* sCo  = sm + C_CO;

    const int t = threadIdx.x;
    const int lane = t & 31, w = t >> 5;
    const int g = lane >> 2, tg = lane & 3;
    uint32_t rank; asm("mov.u32 %0, %%cluster_ctarank;" : "=r"(rank));
    const uint32_t peer = rank ^ 1u;
    const int bh = blockIdx.x >> 1;
    const int b  = bh >> 4, h = bh & 15;
    const uint32_t smb = (uint32_t)__cvta_generic_to_shared(sm);

    const float* w1p = W1g + (size_t)h*HFF*HF4;
    for (int i = t; i < HFF*128; i += 256)
        sW1[(i>>7)*132 + (i&127)] = w1p[(size_t)(i>>7)*HF4 + rank*128 + (i&127)];
    const float* w2p = W2g + (size_t)h*HF4*HFF;
    for (int i = t; i < 128*HFF; i += 256)
        sW2[(i>>6)*72 + (i&63)] = w2p[(size_t)(rank*128 + (i>>6))*HFF + (i&63)];

    const size_t cbase = (size_t)bh * (NCC*CSS*HFF);
    const float* gXC = g_X;
    const float* gXB = g_X + XSZ;
    const float* gXA = g_X + 2*(size_t)XSZ;

    for (int n = 0; n < NCC; n++) {
        {
            const float4* xa4 = (const float4*)(gXA + cbase + (size_t)n*1024);
            const float4* xb4 = (const float4*)(gXB + cbase + (size_t)n*1024);
            const float4* xc4 = (const float4*)(gXC + cbase + (size_t)n*1024);
            int e = t*4, s = e >> 6, f = e & 63;
            *(float4*)(sXA + s*68 + f) = xa4[t];
            *(float4*)(sXB + s*68 + f) = xb4[t];
            *(float4*)(sXC + s*68 + f) = xc4[t];
            if (t < 16) sCo[t] = g_coef[(size_t)bh*(NCC*CSS) + n*CSS + t];
        }
        __syncthreads();

        // P1: Z1loc = XB@W1loc ; Ploc(->Z1b) = XC@W1loc
        {
            const int n0 = w*16;
            float aZ[2][4], aP[2][4];
#pragma unroll
            for (int i=0;i<2;i++)
#pragma unroll
                for (int q=0;q<4;q++){ aZ[i][q]=0.f; aP[i][q]=0.f; }
#pragma unroll
            for (int ks=0; ks<8; ks++){
                int k0 = ks*8;
                uint32_t aBh[4],aBl[4],aCh[4],aCl[4];
                ldAf(sXB, 68, k0, lane, aBh, aBl, 1.f);
                ldAf(sXC, 68, k0, lane, aCh, aCl, 1.f);
#pragma unroll
                for (int nf=0; nf<2; nf++){
                    uint32_t bhf[2], blf[2];
                    ldBf(sW1, 132, k0, n0+nf*8, lane, bhf, blf);
                    mma3(aZ[nf], aBh, aBl, bhf, blf);
                    mma3(aP[nf], aCh, aCl, bhf, blf);
                }
            }
#pragma unroll
            for (int nf=0; nf<2; nf++){
                int col = n0 + nf*8 + 2*tg;
                *(float2*)&sZ1 [g*132 + col]     = make_float2(aZ[nf][0], aZ[nf][1]);
                *(float2*)&sZ1 [(g+8)*132 + col] = make_float2(aZ[nf][2], aZ[nf][3]);
                *(float2*)&sZ1b[g*132 + col]     = make_float2(aP[nf][0], aP[nf][1]);
                *(float2*)&sZ1b[(g+8)*132 + col] = make_float2(aP[nf][2], aP[nf][3]);
            }
        }
        __syncthreads();

        // P2: Z2 partial ; warps 0,1: A1m
        {
            const int n0 = w*8;
            float acc[4] = {0.f,0.f,0.f,0.f};
#pragma unroll 4
            for (int ks=0; ks<16; ks++){
                int k0 = ks*8;
                uint32_t ah[4],al[4],bhf[2],blf[2];
                ldAf(sZ1, 132, k0, lane, ah, al, 1.f);
                ldBf(sW2, 72, k0, n0, lane, bhf, blf);
                mma3(acc, ah, al, bhf, blf);
            }
            {
                int col = n0 + 2*tg;
                *(float2*)&sZ2p[g*72 + col]     = make_float2(acc[0], acc[1]);
                *(float2*)&sZ2p[(g+8)*72 + col] = make_float2(acc[2], acc[3]);
            }
            if (w < 2){
                const int an0 = w*8;
                float a1[4] = {0.f,0.f,0.f,0.f};
#pragma unroll
                for (int ks=0; ks<8; ks++){
                    int k0 = ks*8;
                    uint32_t ah[4],al[4],bhf[2],blf[2];
                    ldAf(sXC, 68, k0, lane, ah, al, 1.f);
                    ldBfT(sXB, 68, k0, an0, lane, bhf, blf);
                    mma3(a1, ah, al, bhf, blf);
                }
                int u0 = an0 + 2*tg;
                int s0 = g, s1 = g+8;
                sA1m[s0*20 + u0]   = (u0   <= s0) ? -sCo[s0]*a1[0] : 0.f;
                sA1m[s0*20 + u0+1] = (u0+1 <= s0) ? -sCo[s0]*a1[1] : 0.f;
                sA1m[s1*20 + u0]   = (u0   <= s1) ? -sCo[s1]*a1[2] : 0.f;
                sA1m[s1*20 + u0+1] = (u0+1 <= s1) ? -sCo[s1]*a1[3] : 0.f;
            }
        }
        CLUSTER_SYNC();

        // g2 = Z2p_own + Z2p_peer - XA
        {
            int row = t >> 4, c4 = (t & 15)*4;
            float4 own = *(float4*)&sZ2p[row*72 + c4];
            float4 pv  = peer_f4(smb + (uint32_t)(C_Z2P + row*72 + c4)*4u, peer);
            float4 xa  = *(float4*)&sXA[row*68 + c4];
            *(float4*)&sG2[row*72 + c4] =
                make_float4(own.x+pv.x-xa.x, own.y+pv.y-xa.y,
                            own.z+pv.z-xa.z, own.w+pv.w-xa.w);
        }
        __syncthreads();

        // P3: g1loc = g2 @ W2loc^T
        {
            const int n0 = w*16;
            float accG[2][4];
#pragma unroll
            for (int i=0;i<2;i++)
#pragma unroll
                for (int q=0;q<4;q++) accG[i][q]=0.f;
#pragma unroll
            for (int ks=0; ks<8; ks++){
                int k0 = ks*8;
                uint32_t ah[4],al[4];
                ldAf(sG2, 72, k0, lane, ah, al, 1.f);
#pragma unroll
                for (int nf=0; nf<2; nf++){
                    uint32_t bhf[2], blf[2];
                    ldBfT(sW2, 72, k0, n0+nf*8, lane, bhf, blf);
                    mma3(accG[nf], ah, al, bhf, blf);
                }
            }
#pragma unroll
            for (int nf=0; nf<2; nf++){
                int col = n0 + nf*8 + 2*tg;
                *(float2*)&sG1[g*132 + col]     = make_float2(accG[nf][0], accG[nf][1]);
                *(float2*)&sG1[(g+8)*132 + col] = make_float2(accG[nf][2], accG[nf][3]);
            }
        }
        __syncthreads();

        // P4: Z1b += A1m@g1loc ; W1loc += (-cl*XB)^T @ g1loc
        {
            const int n0 = w*16;
            float c1[2][4];
#pragma unroll
            for (int i=0;i<2;i++)
#pragma unroll
                for (int q=0;q<4;q++) c1[i][q]=0.f;
#pragma unroll
            for (int ks=0; ks<2; ks++){
                int k0 = ks*8;
                uint32_t ah[4],al[4];
                ldAf(sA1m, 20, k0, lane, ah, al, 1.f);
#pragma unroll
                for (int nf=0; nf<2; nf++){
                    uint32_t bhf[2], blf[2];
                    ldBf(sG1, 132, k0, n0+nf*8, lane, bhf, blf);
                    mma3(c1[nf], ah, al, bhf, blf);
                }
            }
#pragma unroll
            for (int nf=0; nf<2; nf++){
                int col = n0 + nf*8 + 2*tg;
                float2 v0 = *(float2*)&sZ1b[g*132 + col];
                float2 v1 = *(float2*)&sZ1b[(g+8)*132 + col];
                v0.x += c1[nf][0]; v0.y += c1[nf][1];
                v1.x += c1[nf][2]; v1.y += c1[nf][3];
                *(float2*)&sZ1b[g*132 + col]     = v0;
                *(float2*)&sZ1b[(g+8)*132 + col] = v1;
            }
            const float cl = sCo[15];
            const int m0 = (w>>1)*16, nbase = (w&1)*64;
            float wa[8][4];
#pragma unroll
            for (int i=0;i<8;i++)
#pragma unroll
                for (int q=0;q<4;q++) wa[i][q]=0.f;
#pragma unroll
            for (int ks=0; ks<2; ks++){
                int k0 = ks*8;
                uint32_t ah[4],al[4];
                ldAfT(sXB, 68, m0, k0, lane, ah, al, -cl);
#pragma unroll
                for (int nf=0; nf<8; nf++){
                    uint32_t bhf[2], blf[2];
                    ldBf(sG1, 132, k0, nbase + nf*8, lane, bhf, blf);
                    mma3(wa[nf], ah, al, bhf, blf);
                }
            }
#pragma unroll
            for (int nf=0; nf<8; nf++){
                int col = nbase + nf*8 + 2*tg;
                float2 v0 = *(float2*)&sW1[(m0+g)*132 + col];
                float2 v1 = *(float2*)&sW1[(m0+g+8)*132 + col];
                v0.x += wa[nf][0]; v0.y += wa[nf][1];
                v1.x += wa[nf][2]; v1.y += wa[nf][3];
                *(float2*)&sW1[(m0+g)*132 + col]   = v0;
                *(float2*)&sW1[(m0+g+8)*132 + col] = v1;
            }
        }
        __syncthreads();

        // P5: Z2b partial ; A2 partial
        float zacc[4] = {0.f,0.f,0.f,0.f};
        {
            const int n0 = w*8;
#pragma unroll 4
            for (int ks=0; ks<16; ks++){
                int k0 = ks*8;
                uint32_t ah[4],al[4],bhf[2],blf[2];
                ldAf(sZ1b, 132, k0, lane, ah, al, 1.f);
                ldBf(sW2, 72, k0, n0, lane, bhf, blf);
                mma3(zacc, ah, al, bhf, blf);
            }
            {
                int col = n0 + 2*tg;
                *(float2*)&sZ2bp[g*72 + col]     = make_float2(zacc[0], zacc[1]);
                *(float2*)&sZ2bp[(g+8)*72 + col] = make_float2(zacc[2], zacc[3]);
            }
            float pa[2][4];
#pragma unroll
            for (int i=0;i<2;i++)
#pragma unroll
                for (int q=0;q<4;q++) pa[i][q]=0.f;
            const int kb = w*16;
#pragma unroll
            for (int ks=0; ks<2; ks++){
                int k0 = kb + ks*8;
                uint32_t ah[4],al[4];
                ldAf(sZ1b, 132, k0, lane, ah, al, 1.f);
#pragma unroll
                for (int nf=0; nf<2; nf++){
                    uint32_t bhf[2], blf[2];
                    ldBfT(sZ1, 132, k0, nf*8, lane, bhf, blf);
                    mma3(pa[nf], ah, al, bhf, blf);
                }
            }
#pragma unroll
            for (int nf=0; nf<2; nf++){
                int u = nf*8 + 2*tg;
                sSt[w*288 + g*18 + u]       = pa[nf][0];
                sSt[w*288 + g*18 + u+1]     = pa[nf][1];
                sSt[w*288 + (g+8)*18 + u]   = pa[nf][2];
                sSt[w*288 + (g+8)*18 + u+1] = pa[nf][3];
            }
        }
        __syncthreads();

        // P5r: reduce staged A2 partials -> CTA partial
        {
            int s = t >> 4, u = t & 15;
            float sum = 0.f;
#pragma unroll
            for (int ww=0; ww<8; ww++) sum += sSt[ww*288 + s*18 + u];
            sA2p[s*20 + u] = sum;
        }
        CLUSTER_SYNC();

        // A2m = -co*tril(A2_own + A2_peer)
        {
            int s = t >> 4, u = t & 15;
            float pv = peer_f1(smb + (uint32_t)(C_A2P + s*20 + u)*4u, peer);
            float sum = sA2p[s*20 + u] + pv;
            sA2m[s*20 + u] = (u <= s) ? -sCo[s]*sum : 0.f;
        }
        __syncthreads();

        // P6: corr2 ; combine + store ; W2loc update
        {
            const int n0 = w*8;
#pragma unroll
            for (int ks=0; ks<2; ks++){
                int k0 = ks*8;
                uint32_t ah[4],al[4],bhf[2],blf[2];
                ldAf(sA2m, 20, k0, lane, ah, al, 1.f);
                ldBf(sG2, 72, k0, n0, lane, bhf, blf);
                mma3(zacc, ah, al, bhf, blf);
            }
            {
                int srow = rank ? (g+8) : g;
                float2 pv = peer_f2(smb + (uint32_t)(C_Z2BP + srow*72 + n0 + 2*tg)*4u, peer);
                float2 ownv = rank ? make_float2(zacc[2], zacc[3])
                                   : make_float2(zacc[0], zacc[1]);
                int col = h*HFF + n0 + 2*tg;
                size_t ridx = (size_t)(b*LL + n*CSS + srow)*CC + col;
                *(float2*)&g_Z2b[ridx] =
                    make_float2(to_tf32(ownv.x + pv.x), to_tf32(ownv.y + pv.y));
            }
            const float cl = sCo[15];
            const int m0 = w*16;
            float wa[8][4];
#pragma unroll
            for (int i=0;i<8;i++)
#pragma unroll
                for (int q=0;q<4;q++) wa[i][q]=0.f;
#pragma unroll
            for (int ks=0; ks<2; ks++){
                int k0 = ks*8;
                uint32_t ah[4],al[4];
                ldAfT(sZ1, 132, m0, k0, lane, ah, al, -cl);
#pragma unroll
                for (int nf=0; nf<8; nf++){
                    uint32_t bhf[2], blf[2];
                    ldBf(sG2, 72, k0, nf*8, lane, bhf, blf);
                    mma3(wa[nf], ah, al, bhf, blf);
                }
            }
#pragma unroll
            for (int nf=0; nf<8; nf++){
                int col = nf*8 + 2*tg;
                float2 v0 = *(float2*)&sW2[(m0+g)*72 + col];
                float2 v1 = *(float2*)&sW2[(m0+g+8)*72 + col];
                v0.x += wa[nf][0]; v0.y += wa[nf][1];
                v1.x += wa[nf][2]; v1.y += wa[nf][3];
                *(float2*)&sW2[(m0+g)*72 + col]   = v0;
                *(float2*)&sW2[(m0+g+8)*72 + col] = v1;
            }
        }
        __syncthreads();
    }
    CLUSTER_SYNC();
}

// ---------------- launch -----------------
extern "C" void kernel_launch(void* const* d_in, const int* in_sizes, int n_in,
                              void* d_out, int out_size)
{
    const float* hs  = (const float*)d_in[0];
    const float* Wq  = (const float*)d_in[1];
    const float* Wk  = (const float*)d_in[2];
    const float* Wv  = (const float*)d_in[3];
    const float* Wo  = (const float*)d_in[4];
    const float* ilw = (const float*)d_in[5];
    const float* ilb = (const float*)d_in[6];
    const float* W1  = (const float*)d_in[7];
    const float* W2  = (const float*)d_in[8];
    float* out = (float*)d_out;

    cudaFuncSetAttribute(scan_kernel, cudaFuncAttributeMaxDynamicSharedMemorySize,
                         SCAN_SMEM_BYTES);

    void *pX, *pZ2b, *pHsr, *pWT;
    cudaGetSymbolAddress(&pX, g_X);
    cudaGetSymbolAddress(&pZ2b, g_Z2b);
    cudaGetSymbolAddress(&pHsr, g_hsr);
    cudaGetSymbolAddress(&pWT, g_WT);
    float* hsr = (float*)pHsr;
    float* WT  = (float*)pWT;

    // launch 1: round
    round_kernel<<<(size_t)MROWS*CC/4/256, 256>>>(hs, hsr);
    // launch 2: transposes + ilr fused
    transpose3i_kernel<<<dim3(32,32,4), 256>>>(Wq, Wk, Wv, WT, hs, ilw, ilb);
    // launch 3: fused QKV GEMM
    dim3 gq(3*CC/128, MROWS/128);
    gemm_tf32<1><<<gq, 256>>>(hsr, WT, (float*)pX);
    // launch 4: scan (ncu capture slot)
    scan_kernel<<<BB*NHH*2, 256, SCAN_SMEM_BYTES>>>(W1, W2);
    // launch 5-6: Wo transpose + output GEMM
    transpose_kernel<<<dim3(32,32), 256>>>(Wo, WT + 3*(size_t)CC*CC);
    dim3 go(CC/128, MROWS/128);
    gemm_tf32<0><<<go, 256>>>((const float*)pZ2b, WT + 3*(size_t)CC*CC, out);
}

// round 13
// speedup vs baseline: 1.0543x; 1.0329x over previous
#include <cuda_runtime.h>
#include <math.h>
#include <stdint.h>

#define BB 4
#define LL 4096
#define CC 1024
#define NHH 16
#define CSS 16
#define HFF 64
#define HF4 256
#define NCC 256
#define MROWS (BB*LL)   // 16384
#define XSZ (BB*NHH*NCC*CSS*HFF)

// ---------------- device scratch -----------------
__device__ float g_X[3*XSZ];                 // [0]=XC, [1]=XB, [2]=XA (split layout)
__device__ float g_coef[BB*NHH*NCC*CSS];
__device__ float g_Z2b[(size_t)MROWS*CC];
__device__ float g_hsr[(size_t)MROWS*CC];
__device__ float g_WT[4][CC*CC];

// ---------------- helpers -----------------
__device__ __forceinline__ float to_tf32(float x){
    uint32_t u; asm("cvt.rna.tf32.f32 %0, %1;" : "=r"(u) : "f"(x));
    return __uint_as_float(u);
}
__device__ __forceinline__ uint32_t f2tf(float x){
    uint32_t u; asm("cvt.rna.tf32.f32 %0, %1;" : "=r"(u) : "f"(x));
    return u;
}
__device__ __forceinline__ void splitf(float v, uint32_t& h, uint32_t& l){
    h = f2tf(v);
    l = f2tf(v - __uint_as_float(h));
}
__device__ __forceinline__ float2 sp(float v){
    uint32_t h,l; splitf(v,h,l);
    return make_float2(__uint_as_float(h), __uint_as_float(l));
}
__device__ __forceinline__ uint32_t fu(float x){ return __float_as_uint(x); }
__device__ __forceinline__ void ldsm4(uint32_t* r, uint32_t addr){
    asm volatile("ldmatrix.sync.aligned.m8n8.x4.shared.b16 {%0,%1,%2,%3}, [%4];"
        : "=r"(r[0]),"=r"(r[1]),"=r"(r[2]),"=r"(r[3]) : "r"(addr));
}
__device__ __forceinline__ void mma_tf32(float* c, const uint32_t* a, uint32_t b0, uint32_t b1){
    asm volatile("mma.sync.aligned.m16n8k8.row.col.f32.tf32.tf32.f32 "
        "{%0,%1,%2,%3},{%4,%5,%6,%7},{%8,%9},{%0,%1,%2,%3};"
        : "+f"(c[0]),"+f"(c[1]),"+f"(c[2]),"+f"(c[3])
        : "r"(a[0]),"r"(a[1]),"r"(a[2]),"r"(a[3]),"r"(b0),"r"(b1));
}
__device__ __forceinline__ void mma3(float* c, const uint32_t* ah, const uint32_t* al,
                                     const uint32_t* bh, const uint32_t* bl){
    mma_tf32(c, ah, bh[0], bh[1]);
    mma_tf32(c, ah, bl[0], bl[1]);
    mma_tf32(c, al, bh[0], bh[1]);
}
// raw split-at-consume loader (W1 only)
__device__ __forceinline__ void ldBf(const float* S, int ld, int k0, int n0, int lane,
                                     uint32_t* bh, uint32_t* bl){
    int g = lane >> 2, tg = lane & 3;
    splitf(S[(k0+tg)*ld + n0+g],   bh[0], bl[0]);
    splitf(S[(k0+tg+4)*ld + n0+g], bh[1], bl[1]);
}
// twin-array loaders (pre-split)
__device__ __forceinline__ void ldAf2(const float* Sh, const float* Sl, int ld, int k0,
                                      int lane, uint32_t* ah, uint32_t* al){
    int g = lane >> 2, tg = lane & 3;
    ah[0]=fu(Sh[g*ld + k0+tg]);       al[0]=fu(Sl[g*ld + k0+tg]);
    ah[1]=fu(Sh[(g+8)*ld + k0+tg]);   al[1]=fu(Sl[(g+8)*ld + k0+tg]);
    ah[2]=fu(Sh[g*ld + k0+tg+4]);     al[2]=fu(Sl[g*ld + k0+tg+4]);
    ah[3]=fu(Sh[(g+8)*ld + k0+tg+4]); al[3]=fu(Sl[(g+8)*ld + k0+tg+4]);
}
__device__ __forceinline__ void ldAfT2(const float* Sh, const float* Sl, int ld, int m0,
                                       int k0, int lane, uint32_t* ah, uint32_t* al){
    int g = lane >> 2, tg = lane & 3;
    ah[0]=fu(Sh[(k0+tg)*ld + m0+g]);     al[0]=fu(Sl[(k0+tg)*ld + m0+g]);
    ah[1]=fu(Sh[(k0+tg)*ld + m0+g+8]);   al[1]=fu(Sl[(k0+tg)*ld + m0+g+8]);
    ah[2]=fu(Sh[(k0+tg+4)*ld + m0+g]);   al[2]=fu(Sl[(k0+tg+4)*ld + m0+g]);
    ah[3]=fu(Sh[(k0+tg+4)*ld + m0+g+8]); al[3]=fu(Sl[(k0+tg+4)*ld + m0+g+8]);
}
__device__ __forceinline__ void ldBf2(const float* Sh, const float* Sl, int ld, int k0,
                                      int n0, int lane, uint32_t* bh, uint32_t* bl){
    int g = lane >> 2, tg = lane & 3;
    bh[0]=fu(Sh[(k0+tg)*ld + n0+g]);   bl[0]=fu(Sl[(k0+tg)*ld + n0+g]);
    bh[1]=fu(Sh[(k0+tg+4)*ld + n0+g]); bl[1]=fu(Sl[(k0+tg+4)*ld + n0+g]);
}
__device__ __forceinline__ void ldBfT2(const float* Sh, const float* Sl, int ld, int k0,
                                       int n0, int lane, uint32_t* bh, uint32_t* bl){
    int g = lane >> 2, tg = lane & 3;
    bh[0]=fu(Sh[(n0+g)*ld + k0+tg]);   bl[0]=fu(Sl[(n0+g)*ld + k0+tg]);
    bh[1]=fu(Sh[(n0+g)*ld + k0+tg+4]); bl[1]=fu(Sl[(n0+g)*ld + k0+tg+4]);
}

// ---------------- cluster helpers -----------------
#define CLUSTER_SYNC() do{ \
    asm volatile("barrier.cluster.arrive.aligned;" ::: "memory"); \
    asm volatile("barrier.cluster.wait.aligned;"   ::: "memory"); }while(0)

__device__ __forceinline__ uint32_t mapa_u32(uint32_t laddr, uint32_t rank){
    uint32_t ra; asm("mapa.shared::cluster.u32 %0, %1, %2;" : "=r"(ra) : "r"(laddr), "r"(rank));
    return ra;
}
__device__ __forceinline__ float4 peer_f4(uint32_t laddr, uint32_t peer){
    uint32_t ra = mapa_u32(laddr, peer);
    float4 v;
    asm volatile("ld.shared::cluster.v4.f32 {%0,%1,%2,%3}, [%4];"
        : "=f"(v.x),"=f"(v.y),"=f"(v.z),"=f"(v.w) : "r"(ra));
    return v;
}
__device__ __forceinline__ float2 peer_f2(uint32_t laddr, uint32_t peer){
    uint32_t ra = mapa_u32(laddr, peer);
    float2 v;
    asm volatile("ld.shared::cluster.v2.f32 {%0,%1}, [%2];"
        : "=f"(v.x),"=f"(v.y) : "r"(ra));
    return v;
}
__device__ __forceinline__ float peer_f1(uint32_t laddr, uint32_t peer){
    uint32_t ra = mapa_u32(laddr, peer);
    float v;
    asm volatile("ld.shared::cluster.f32 %0, [%1];" : "=f"(v) : "r"(ra));
    return v;
}

// ---------------- prep kernels -----------------
__global__ void __launch_bounds__(256) round_kernel(const float* __restrict__ in,
                                                    float* __restrict__ out){
    size_t i = (size_t)blockIdx.x*256 + threadIdx.x;
    float4 v = ((const float4*)in)[i];
    ((float4*)out)[i] = make_float4(to_tf32(v.x), to_tf32(v.y), to_tf32(v.z), to_tf32(v.w));
}
__global__ void __launch_bounds__(256) transpose3i_kernel(const float* __restrict__ Wq,
                                                          const float* __restrict__ Wk,
                                                          const float* __restrict__ Wv,
                                                          float* __restrict__ out,
                                                          const float* __restrict__ hs,
                                                          const float* __restrict__ ilw,
                                                          const float* __restrict__ ilb){
    if (blockIdx.z < 3){
        __shared__ float tile[32][33];
        const float* in = (blockIdx.z==0) ? Wq : (blockIdx.z==1) ? Wk : Wv;
        float* o = out + (size_t)blockIdx.z*CC*CC;
        int bx = blockIdx.x*32, by = blockIdx.y*32;
        int tx = threadIdx.x & 31, ty = threadIdx.x >> 5;
        for (int r = ty; r < 32; r += 8)
            tile[r][tx] = in[(size_t)(by+r)*CC + bx + tx];
        __syncthreads();
        for (int r = ty; r < 32; r += 8)
            o[(size_t)(bx+r)*CC + by + tx] = to_tf32(tile[tx][r]);
    } else {
        int blk = blockIdx.y*32 + blockIdx.x;
        int h = threadIdx.x & 15, rloc = threadIdx.x >> 4;
        int row = blk*16 + rloc;
        const float* hp = hs + (size_t)row*CC;
        float a0=0.f,a1=0.f,a2=0.f,a3=0.f;
        for (int k=0;k<CC;k+=4){
            float4 x = *(const float4*)(hp + k);
            a0 += x.x*ilw[(k+0)*NHH+h];
            a1 += x.y*ilw[(k+1)*NHH+h];
            a2 += x.z*ilw[(k+2)*NHH+h];
            a3 += x.w*ilw[(k+3)*NHH+h];
        }
        float acc = (a0+a1)+(a2+a3) + ilb[h];
        float sig = 1.f/(1.f+expf(-acc));
        int b = row>>12, l = row&4095, n = l>>4, s = l&15;
        g_coef[((size_t)(b*NHH+h)*NCC+n)*CSS+s] = sig*(1.f/(float)(s+1))*(1.f/(float)HFF);
    }
}
__global__ void __launch_bounds__(256) transpose_kernel(const float* __restrict__ in,
                                                        float* __restrict__ out){
    __shared__ float tile[32][33];
    int bx = blockIdx.x*32, by = blockIdx.y*32;
    int tx = threadIdx.x & 31, ty = threadIdx.x >> 5;
    for (int r = ty; r < 32; r += 8)
        tile[r][tx] = in[(size_t)(by+r)*CC + bx + tx];
    __syncthreads();
    for (int r = ty; r < 32; r += 8)
        out[(size_t)(bx+r)*CC + by + tx] = to_tf32(tile[tx][r]);
}

// ---------------- tf32 GEMM (R8 core, fused-QKV epilogue; unchanged) ---------
#define GPAD 36
template<int SPLIT>
__global__ void __launch_bounds__(256) gemm_tf32(const float* __restrict__ A,
                                                 const float* __restrict__ BT,
                                                 float* __restrict__ out)
{
    __shared__ float As[128*GPAD];
    __shared__ float Bs[128*GPAD];
    const int t = threadIdx.x, lane = t & 31, warp = t >> 5;
    const int wm = warp >> 1, wn = warp & 1;
    const int bm = blockIdx.y, bn = blockIdx.x;

    float acc[2][8][4];
#pragma unroll
    for (int i=0;i<2;i++)
#pragma unroll
        for (int j=0;j<8;j++)
#pragma unroll
            for (int q=0;q<4;q++) acc[i][j][q]=0.f;

    const uint32_t As_u = (uint32_t)__cvta_generic_to_shared(As);
    const uint32_t Bs_u = (uint32_t)__cvta_generic_to_shared(Bs);
    uint32_t a_addr[2], b_addr[4];
#pragma unroll
    for (int mf=0; mf<2; mf++){
        int row = wm*32 + mf*16 + (lane & 15);
        a_addr[mf] = As_u + (uint32_t)(row*GPAD + (lane>>4)*4)*4u;
    }
#pragma unroll
    for (int nf2=0; nf2<4; nf2++){
        int nr = wn*64 + nf2*16 + (lane & 7) + ((lane>>4)&1)*8;
        b_addr[nf2] = Bs_u + (uint32_t)(nr*GPAD + ((lane>>3)&1)*4)*4u;
    }

    const float* Ab  = A  + (size_t)(bm*128)*CC;
    const float* BTb = BT + (size_t)(bn*128)*CC;
    const int row = t >> 3, k4 = (t & 7)*4;

    float4 ar[4], br[4];
#pragma unroll
    for (int i=0;i<4;i++){
        int r = row + i*32;
        ar[i] = *(const float4*)(Ab  + (size_t)r*CC + k4);
        br[i] = *(const float4*)(BTb + (size_t)r*CC + k4);
    }

    for (int it=0; it<32; it++){
        __syncthreads();
#pragma unroll
        for (int i=0;i<4;i++){
            int r = row + i*32;
            *(float4*)&As[r*GPAD + k4] = ar[i];
            *(float4*)&Bs[r*GPAD + k4] = br[i];
        }
        __syncthreads();
        if (it < 31){
            const int kb = (it+1)*32;
#pragma unroll
            for (int i=0;i<4;i++){
                int r = row + i*32;
                ar[i] = *(const float4*)(Ab  + (size_t)r*CC + kb + k4);
                br[i] = *(const float4*)(BTb + (size_t)r*CC + kb + k4);
            }
        }
#pragma unroll
        for (int s8=0; s8<4; s8++){
            uint32_t a[2][4], bf[4][4];
            ldsm4(a[0], a_addr[0] + s8*32);
            ldsm4(a[1], a_addr[1] + s8*32);
            ldsm4(bf[0], b_addr[0] + s8*32);
            ldsm4(bf[1], b_addr[1] + s8*32);
            ldsm4(bf[2], b_addr[2] + s8*32);
            ldsm4(bf[3], b_addr[3] + s8*32);
#pragma unroll
            for (int nf=0; nf<8; nf++){
                uint32_t b0 = bf[nf>>1][(nf&1)*2], b1 = bf[nf>>1][(nf&1)*2+1];
                mma_tf32(acc[0][nf], a[0], b0, b1);
                mma_tf32(acc[1][nf], a[1], b0, b1);
            }
        }
    }

#pragma unroll
    for (int mf=0; mf<2; mf++){
#pragma unroll
        for (int nf=0; nf<8; nf++){
            int r = bm*128 + wm*32 + mf*16 + (lane>>2);
            int c = bn*128 + wn*64 + nf*8 + (lane&3)*2;
#pragma unroll
            for (int half=0; half<2; half++){
                int rr = r + half*8;
                float2 v = make_float2(acc[mf][nf][half*2], acc[mf][nf][half*2+1]);
                if (SPLIT){
                    int proj = c >> 10, cc = c & 1023;
                    int b = rr >> 12, l = rr & 4095;
                    int n = l >> 4, s = l & 15;
                    int h = cc >> 6, f = cc & 63;
                    size_t idx = (size_t)proj*XSZ +
                                 ((((size_t)(b*NHH + h)*NCC + n)*CSS + s)*HFF + f);
                    *(float2*)(out + idx) = v;
                } else {
                    *(float2*)(out + (size_t)rr*CC + c) = v;
                }
            }
        }
    }
}

// ---------------- TTT scan: 2-CTA cluster, twin hi/lo split caches -----------
#define D_W1    0                        // raw 64x132
#define D_W2H   (D_W1 + 64*132)
#define D_W2L   (D_W2H + 128*72)
#define D_XA    (D_W2L + 128*72)         // raw 16x68
#define D_XBH   (D_XA + 16*68)
#define D_XBL   (D_XBH + 16*68)
#define D_XCH   (D_XBL + 16*68)
#define D_XCL   (D_XCH + 16*68)
#define D_Z1H   (D_XCL + 16*68)          // 16x132
#define D_Z1L   (D_Z1H + 16*132)
#define D_Z1BH  (D_Z1L + 16*132)
#define D_Z1BL  (D_Z1BH + 16*132)
#define D_G1H   (D_Z1BL + 16*132)
#define D_G1L   (D_G1H + 16*132)
#define D_G2H   (D_G1L + 16*132)         // 16x72
#define D_G2L   (D_G2H + 16*72)
#define D_Z2P   (D_G2L + 16*72)          // raw 16x72 (DSMEM)
#define D_Z2BP  (D_Z2P + 16*72)          // raw 16x72 (DSMEM)
#define D_A1MH  (D_Z2BP + 16*72)         // 16x20
#define D_A1ML  (D_A1MH + 16*20)
#define D_A2MH  (D_A1ML + 16*20)
#define D_A2ML  (D_A2MH + 16*20)
#define D_A2P   (D_A2ML + 16*20)         // raw 16x20 (DSMEM)
#define D_ST    (D_A2P + 16*20)          // 8x16x18
#define D_CO    (D_ST + 8*16*18)
#define SCAN_SMEM_FLOATS (D_CO + 16)
#define SCAN_SMEM_BYTES  (SCAN_SMEM_FLOATS*4)

__global__ void __launch_bounds__(256,1) __cluster_dims__(2,1,1)
scan_kernel(const float* __restrict__ W1g, const float* __restrict__ W2g)
{
    extern __shared__ float sm[];
    float* sW1   = sm + D_W1;
    float* sW2h  = sm + D_W2H;
    float* sW2l  = sm + D_W2L;
    float* sXA   = sm + D_XA;
    float* sXBh  = sm + D_XBH;
    float* sXBl  = sm + D_XBL;
    float* sXCh  = sm + D_XCH;
    float* sXCl  = sm + D_XCL;
    float* sZ1h  = sm + D_Z1H;
    float* sZ1l  = sm + D_Z1L;
    float* sZ1bh = sm + D_Z1BH;
    float* sZ1bl = sm + D_Z1BL;
    float* sG1h  = sm + D_G1H;
    float* sG1l  = sm + D_G1L;
    float* sG2h  = sm + D_G2H;
    float* sG2l  = sm + D_G2L;
    float* sZ2p  = sm + D_Z2P;
    float* sZ2bp = sm + D_Z2BP;
    float* sA1mh = sm + D_A1MH;
    float* sA1ml = sm + D_A1ML;
    float* sA2mh = sm + D_A2MH;
    float* sA2ml = sm + D_A2ML;
    float* sA2p  = sm + D_A2P;
    float* sSt   = sm + D_ST;
    float* sCo   = sm + D_CO;

    const int t = threadIdx.x;
    const int lane = t & 31, w = t >> 5;
    const int g = lane >> 2, tg = lane & 3;
    uint32_t rank; asm("mov.u32 %0, %%cluster_ctarank;" : "=r"(rank));
    const uint32_t peer = rank ^ 1u;
    const int bh = blockIdx.x >> 1;
    const int b  = bh >> 4, h = bh & 15;
    const uint32_t smb = (uint32_t)__cvta_generic_to_shared(sm);

    const float* w1p = W1g + (size_t)h*HFF*HF4;
    for (int i = t; i < HFF*128; i += 256)
        sW1[(i>>7)*132 + (i&127)] = w1p[(size_t)(i>>7)*HF4 + rank*128 + (i&127)];
    const float* w2p = W2g + (size_t)h*HF4*HFF;
    for (int i = t; i < 128*HFF; i += 256){
        int k = i>>6, f = i&63;
        float2 v = sp(w2p[(size_t)(rank*128 + k)*HFF + f]);
        sW2h[k*72 + f] = v.x;
        sW2l[k*72 + f] = v.y;
    }

    const size_t cbase = (size_t)bh * (NCC*CSS*HFF);
    const float* gXC = g_X;
    const float* gXB = g_X + XSZ;
    const float* gXA = g_X + 2*(size_t)XSZ;

    for (int n = 0; n < NCC; n++) {
        // ---- chunk load: XA raw; XB/XC pre-split to twin arrays ----
        {
            const float4* xa4 = (const float4*)(gXA + cbase + (size_t)n*1024);
            const float4* xb4 = (const float4*)(gXB + cbase + (size_t)n*1024);
            const float4* xc4 = (const float4*)(gXC + cbase + (size_t)n*1024);
            int e = t*4, s = e >> 6, f = e & 63;
            float4 va = xa4[t], vb = xb4[t], vc = xc4[t];
            *(float4*)(sXA + s*68 + f) = va;
            float2 b0=sp(vb.x), b1=sp(vb.y), b2=sp(vb.z), b3=sp(vb.w);
            *(float4*)&sXBh[s*68 + f] = make_float4(b0.x,b1.x,b2.x,b3.x);
            *(float4*)&sXBl[s*68 + f] = make_float4(b0.y,b1.y,b2.y,b3.y);
            float2 c0=sp(vc.x), c1_=sp(vc.y), c2=sp(vc.z), c3=sp(vc.w);
            *(float4*)&sXCh[s*68 + f] = make_float4(c0.x,c1_.x,c2.x,c3.x);
            *(float4*)&sXCl[s*68 + f] = make_float4(c0.y,c1_.y,c2.y,c3.y);
            if (t < 16) sCo[t] = g_coef[(size_t)bh*(NCC*CSS) + n*CSS + t];
        }
        __syncthreads();

        // ---- P1: Z1loc = XB@W1loc ; Ploc = XC@W1loc -> twin stores ----
        {
            const int n0 = w*16;
            float aZ[2][4], aP[2][4];
#pragma unroll
            for (int i=0;i<2;i++)
#pragma unroll
                for (int q=0;q<4;q++){ aZ[i][q]=0.f; aP[i][q]=0.f; }
#pragma unroll
            for (int ks=0; ks<8; ks++){
                int k0 = ks*8;
                uint32_t aBh[4],aBl[4],aCh[4],aCl[4];
                ldAf2(sXBh, sXBl, 68, k0, lane, aBh, aBl);
                ldAf2(sXCh, sXCl, 68, k0, lane, aCh, aCl);
#pragma unroll
                for (int nf=0; nf<2; nf++){
                    uint32_t bhf[2], blf[2];
                    ldBf(sW1, 132, k0, n0+nf*8, lane, bhf, blf);
                    mma3(aZ[nf], aBh, aBl, bhf, blf);
                    mma3(aP[nf], aCh, aCl, bhf, blf);
                }
            }
#pragma unroll
            for (int nf=0; nf<2; nf++){
                int col = n0 + nf*8 + 2*tg;
                float2 z0=sp(aZ[nf][0]), z1=sp(aZ[nf][1]), z2=sp(aZ[nf][2]), z3=sp(aZ[nf][3]);
                *(float2*)&sZ1h[g*132 + col]     = make_float2(z0.x, z1.x);
                *(float2*)&sZ1l[g*132 + col]     = make_float2(z0.y, z1.y);
                *(float2*)&sZ1h[(g+8)*132 + col] = make_float2(z2.x, z3.x);
                *(float2*)&sZ1l[(g+8)*132 + col] = make_float2(z2.y, z3.y);
                float2 p0=sp(aP[nf][0]), p1=sp(aP[nf][1]), p2=sp(aP[nf][2]), p3=sp(aP[nf][3]);
                *(float2*)&sZ1bh[g*132 + col]     = make_float2(p0.x, p1.x);
                *(float2*)&sZ1bl[g*132 + col]     = make_float2(p0.y, p1.y);
                *(float2*)&sZ1bh[(g+8)*132 + col] = make_float2(p2.x, p3.x);
                *(float2*)&sZ1bl[(g+8)*132 + col] = make_float2(p2.y, p3.y);
            }
        }
        __syncthreads();

        // ---- P2: Z2 partial ; warps 0,1: A1m twins ----
        {
            const int n0 = w*8;
            float acc[4] = {0.f,0.f,0.f,0.f};
#pragma unroll 4
            for (int ks=0; ks<16; ks++){
                int k0 = ks*8;
                uint32_t ah[4],al[4],bhf[2],blf[2];
                ldAf2(sZ1h, sZ1l, 132, k0, lane, ah, al);
                ldBf2(sW2h, sW2l, 72, k0, n0, lane, bhf, blf);
                mma3(acc, ah, al, bhf, blf);
            }
            {
                int col = n0 + 2*tg;
                *(float2*)&sZ2p[g*72 + col]     = make_float2(acc[0], acc[1]);
                *(float2*)&sZ2p[(g+8)*72 + col] = make_float2(acc[2], acc[3]);
            }
            if (w < 2){
                const int an0 = w*8;
                float a1[4] = {0.f,0.f,0.f,0.f};
#pragma unroll
                for (int ks=0; ks<8; ks++){
                    int k0 = ks*8;
                    uint32_t ah[4],al[4],bhf[2],blf[2];
                    ldAf2(sXCh, sXCl, 68, k0, lane, ah, al);
                    ldBfT2(sXBh, sXBl, 68, k0, an0, lane, bhf, blf);
                    mma3(a1, ah, al, bhf, blf);
                }
                int u0 = an0 + 2*tg;
                int s0 = g, s1 = g+8;
                float2 q;
                q = (u0   <= s0) ? sp(-sCo[s0]*a1[0]) : make_float2(0.f,0.f);
                sA1mh[s0*20 + u0] = q.x;   sA1ml[s0*20 + u0] = q.y;
                q = (u0+1 <= s0) ? sp(-sCo[s0]*a1[1]) : make_float2(0.f,0.f);
                sA1mh[s0*20 + u0+1] = q.x; sA1ml[s0*20 + u0+1] = q.y;
                q = (u0   <= s1) ? sp(-sCo[s1]*a1[2]) : make_float2(0.f,0.f);
                sA1mh[s1*20 + u0] = q.x;   sA1ml[s1*20 + u0] = q.y;
                q = (u0+1 <= s1) ? sp(-sCo[s1]*a1[3]) : make_float2(0.f,0.f);
                sA1mh[s1*20 + u0+1] = q.x; sA1ml[s1*20 + u0+1] = q.y;
            }
        }
        CLUSTER_SYNC();

        // ---- g2 = Z2p_own + Z2p_peer - XA -> twin stores ----
        {
            int row = t >> 4, c4 = (t & 15)*4;
            float4 own = *(float4*)&sZ2p[row*72 + c4];
            float4 pv  = peer_f4(smb + (uint32_t)(D_Z2P + row*72 + c4)*4u, peer);
            float4 xa  = *(float4*)&sXA[row*68 + c4];
            float2 g0 = sp(own.x+pv.x-xa.x), g1_ = sp(own.y+pv.y-xa.y);
            float2 g2_ = sp(own.z+pv.z-xa.z), g3 = sp(own.w+pv.w-xa.w);
            *(float4*)&sG2h[row*72 + c4] = make_float4(g0.x,g1_.x,g2_.x,g3.x);
            *(float4*)&sG2l[row*72 + c4] = make_float4(g0.y,g1_.y,g2_.y,g3.y);
        }
        __syncthreads();

        // ---- P3: g1loc = g2 @ W2loc^T -> twin stores ----
        {
            const int n0 = w*16;
            float accG[2][4];
#pragma unroll
            for (int i=0;i<2;i++)
#pragma unroll
                for (int q=0;q<4;q++) accG[i][q]=0.f;
#pragma unroll
            for (int ks=0; ks<8; ks++){
                int k0 = ks*8;
                uint32_t ah[4],al[4];
                ldAf2(sG2h, sG2l, 72, k0, lane, ah, al);
#pragma unroll
                for (int nf=0; nf<2; nf++){
                    uint32_t bhf[2], blf[2];
                    ldBfT2(sW2h, sW2l, 72, k0, n0+nf*8, lane, bhf, blf);
                    mma3(accG[nf], ah, al, bhf, blf);
                }
            }
#pragma unroll
            for (int nf=0; nf<2; nf++){
                int col = n0 + nf*8 + 2*tg;
                float2 q0=sp(accG[nf][0]), q1=sp(accG[nf][1]), q2=sp(accG[nf][2]), q3=sp(accG[nf][3]);
                *(float2*)&sG1h[g*132 + col]     = make_float2(q0.x, q1.x);
                *(float2*)&sG1l[g*132 + col]     = make_float2(q0.y, q1.y);
                *(float2*)&sG1h[(g+8)*132 + col] = make_float2(q2.x, q3.x);
                *(float2*)&sG1l[(g+8)*132 + col] = make_float2(q2.y, q3.y);
            }
        }
        __syncthreads();

        // ---- P4: Z1b += A1m@g1loc ; W1 -= cl*(XB^T@g1loc) ----
        {
            const int n0 = w*16;
            float c1[2][4];
#pragma unroll
            for (int i=0;i<2;i++)
#pragma unroll
                for (int q=0;q<4;q++) c1[i][q]=0.f;
#pragma unroll
            for (int ks=0; ks<2; ks++){
                int k0 = ks*8;
                uint32_t ah[4],al[4];
                ldAf2(sA1mh, sA1ml, 20, k0, lane, ah, al);
#pragma unroll
                for (int nf=0; nf<2; nf++){
                    uint32_t bhf[2], blf[2];
                    ldBf2(sG1h, sG1l, 132, k0, n0+nf*8, lane, bhf, blf);
                    mma3(c1[nf], ah, al, bhf, blf);
                }
            }
#pragma unroll
            for (int nf=0; nf<2; nf++){
                int col = n0 + nf*8 + 2*tg;
                float2 h0 = *(float2*)&sZ1bh[g*132 + col];
                float2 l0 = *(float2*)&sZ1bl[g*132 + col];
                float2 h1 = *(float2*)&sZ1bh[(g+8)*132 + col];
                float2 l1 = *(float2*)&sZ1bl[(g+8)*132 + col];
                float2 s00 = sp(h0.x + l0.x + c1[nf][0]);
                float2 s01 = sp(h0.y + l0.y + c1[nf][1]);
                float2 s10 = sp(h1.x + l1.x + c1[nf][2]);
                float2 s11 = sp(h1.y + l1.y + c1[nf][3]);
                *(float2*)&sZ1bh[g*132 + col]     = make_float2(s00.x, s01.x);
                *(float2*)&sZ1bl[g*132 + col]     = make_float2(s00.y, s01.y);
                *(float2*)&sZ1bh[(g+8)*132 + col] = make_float2(s10.x, s11.x);
                *(float2*)&sZ1bl[(g+8)*132 + col] = make_float2(s10.y, s11.y);
            }
            const float cl = sCo[15];
            const int m0 = (w>>1)*16, nbase = (w&1)*64;
            float wa[8][4];
#pragma unroll
            for (int i=0;i<8;i++)
#pragma unroll
                for (int q=0;q<4;q++) wa[i][q]=0.f;
#pragma unroll
            for (int ks=0; ks<2; ks++){
                int k0 = ks*8;
                uint32_t ah[4],al[4];
                ldAfT2(sXBh, sXBl, 68, m0, k0, lane, ah, al);
#pragma unroll
                for (int nf=0; nf<8; nf++){
                    uint32_t bhf[2], blf[2];
                    ldBf2(sG1h, sG1l, 132, k0, nbase + nf*8, lane, bhf, blf);
                    mma3(wa[nf], ah, al, bhf, blf);
                }
            }
#pragma unroll
            for (int nf=0; nf<8; nf++){
                int col = nbase + nf*8 + 2*tg;
                float2 v0 = *(float2*)&sW1[(m0+g)*132 + col];
                float2 v1 = *(float2*)&sW1[(m0+g+8)*132 + col];
                v0.x -= cl*wa[nf][0]; v0.y -= cl*wa[nf][1];
                v1.x -= cl*wa[nf][2]; v1.y -= cl*wa[nf][3];
                *(float2*)&sW1[(m0+g)*132 + col]   = v0;
                *(float2*)&sW1[(m0+g+8)*132 + col] = v1;
            }
        }
        __syncthreads();

        // ---- P5: Z2b partial ; A2 partial ----
        float zacc[4] = {0.f,0.f,0.f,0.f};
        {
            const int n0 = w*8;
#pragma unroll 4
            for (int ks=0; ks<16; ks++){
                int k0 = ks*8;
                uint32_t ah[4],al[4],bhf[2],blf[2];
                ldAf2(sZ1bh, sZ1bl, 132, k0, lane, ah, al);
                ldBf2(sW2h, sW2l, 72, k0, n0, lane, bhf, blf);
                mma3(zacc, ah, al, bhf, blf);
            }
            {
                int col = n0 + 2*tg;
                *(float2*)&sZ2bp[g*72 + col]     = make_float2(zacc[0], zacc[1]);
                *(float2*)&sZ2bp[(g+8)*72 + col] = make_float2(zacc[2], zacc[3]);
            }
            float pa[2][4];
#pragma unroll
            for (int i=0;i<2;i++)
#pragma unroll
                for (int q=0;q<4;q++) pa[i][q]=0.f;
            const int kb = w*16;
#pragma unroll
            for (int ks=0; ks<2; ks++){
                int k0 = kb + ks*8;
                uint32_t ah[4],al[4];
                ldAf2(sZ1bh, sZ1bl, 132, k0, lane, ah, al);
#pragma unroll
                for (int nf=0; nf<2; nf++){
                    uint32_t bhf[2], blf[2];
                    ldBfT2(sZ1h, sZ1l, 132, k0, nf*8, lane, bhf, blf);
                    mma3(pa[nf], ah, al, bhf, blf);
                }
            }
#pragma unroll
            for (int nf=0; nf<2; nf++){
                int u = nf*8 + 2*tg;
                sSt[w*288 + g*18 + u]       = pa[nf][0];
                sSt[w*288 + g*18 + u+1]     = pa[nf][1];
                sSt[w*288 + (g+8)*18 + u]   = pa[nf][2];
                sSt[w*288 + (g+8)*18 + u+1] = pa[nf][3];
            }
        }
        __syncthreads();

        // ---- P5r: reduce staged A2 partials -> CTA partial (raw) ----
        {
            int s = t >> 4, u = t & 15;
            float sum = 0.f;
#pragma unroll
            for (int ww=0; ww<8; ww++) sum += sSt[ww*288 + s*18 + u];
            sA2p[s*20 + u] = sum;
        }
        CLUSTER_SYNC();

        // ---- A2m twins = split(-co*tril(A2_own + A2_peer)) ----
        {
            int s = t >> 4, u = t & 15;
            float pv = peer_f1(smb + (uint32_t)(D_A2P + s*20 + u)*4u, peer);
            float sum = sA2p[s*20 + u] + pv;
            float2 q = (u <= s) ? sp(-sCo[s]*sum) : make_float2(0.f,0.f);
            sA2mh[s*20 + u] = q.x;
            sA2ml[s*20 + u] = q.y;
        }
        __syncthreads();

        // ---- P6: corr2 ; combine + store ; W2 twin update ----
        {
            const int n0 = w*8;
#pragma unroll
            for (int ks=0; ks<2; ks++){
                int k0 = ks*8;
                uint32_t ah[4],al[4],bhf[2],blf[2];
                ldAf2(sA2mh, sA2ml, 20, k0, lane, ah, al);
                ldBf2(sG2h, sG2l, 72, k0, n0, lane, bhf, blf);
                mma3(zacc, ah, al, bhf, blf);
            }
            {
                int srow = rank ? (g+8) : g;
                float2 pv = peer_f2(smb + (uint32_t)(D_Z2BP + srow*72 + n0 + 2*tg)*4u, peer);
                float2 ownv = rank ? make_float2(zacc[2], zacc[3])
                                   : make_float2(zacc[0], zacc[1]);
                int col = h*HFF + n0 + 2*tg;
                size_t ridx = (size_t)(b*LL + n*CSS + srow)*CC + col;
                *(float2*)&g_Z2b[ridx] =
                    make_float2(to_tf32(ownv.x + pv.x), to_tf32(ownv.y + pv.y));
            }
            const float cl = sCo[15];
            const int m0 = w*16;
            float wa[8][4];
#pragma unroll
            for (int i=0;i<8;i++)
#pragma unroll
                for (int q=0;q<4;q++) wa[i][q]=0.f;
#pragma unroll
            for (int ks=0; ks<2; ks++){
                int k0 = ks*8;
                uint32_t ah[4],al[4];
                ldAfT2(sZ1h, sZ1l, 132, m0, k0, lane, ah, al);
#pragma unroll
                for (int nf=0; nf<8; nf++){
                    uint32_t bhf[2], blf[2];
                    ldBf2(sG2h, sG2l, 72, k0, nf*8, lane, bhf, blf);
                    mma3(wa[nf], ah, al, bhf, blf);
                }
            }
#pragma unroll
            for (int nf=0; nf<8; nf++){
                int col = nf*8 + 2*tg;
                float2 h0 = *(float2*)&sW2h[(m0+g)*72 + col];
                float2 l0 = *(float2*)&sW2l[(m0+g)*72 + col];
                float2 h1 = *(float2*)&sW2h[(m0+g+8)*72 + col];
                float2 l1 = *(float2*)&sW2l[(m0+g+8)*72 + col];
                float2 sa = sp(h0.x + l0.x - cl*wa[nf][0]);
                float2 sb = sp(h0.y + l0.y - cl*wa[nf][1]);
                float2 sc = sp(h1.x + l1.x - cl*wa[nf][2]);
                float2 sd = sp(h1.y + l1.y - cl*wa[nf][3]);
                *(float2*)&sW2h[(m0+g)*72 + col]   = make_float2(sa.x, sb.x);
                *(float2*)&sW2l[(m0+g)*72 + col]   = make_float2(sa.y, sb.y);
                *(float2*)&sW2h[(m0+g+8)*72 + col] = make_float2(sc.x, sd.x);
                *(float2*)&sW2l[(m0+g+8)*72 + col] = make_float2(sc.y, sd.y);
            }
        }
        __syncthreads();
    }
    CLUSTER_SYNC();
}

// ---------------- launch -----------------
extern "C" void kernel_launch(void* const* d_in, const int* in_sizes, int n_in,
                              void* d_out, int out_size)
{
    const float* hs  = (const float*)d_in[0];
    const float* Wq  = (const float*)d_in[1];
    const float* Wk  = (const float*)d_in[2];
    const float* Wv  = (const float*)d_in[3];
    const float* Wo  = (const float*)d_in[4];
    const float* ilw = (const float*)d_in[5];
    const float* ilb = (const float*)d_in[6];
    const float* W1  = (const float*)d_in[7];
    const float* W2  = (const float*)d_in[8];
    float* out = (float*)d_out;

    cudaFuncSetAttribute(scan_kernel, cudaFuncAttributeMaxDynamicSharedMemorySize,
                         SCAN_SMEM_BYTES);

    void *pX, *pZ2b, *pHsr, *pWT;
    cudaGetSymbolAddress(&pX, g_X);
    cudaGetSymbolAddress(&pZ2b, g_Z2b);
    cudaGetSymbolAddress(&pHsr, g_hsr);
    cudaGetSymbolAddress(&pWT, g_WT);
    float* hsr = (float*)pHsr;
    float* WT  = (float*)pWT;

    // launch 1: round
    round_kernel<<<(size_t)MROWS*CC/4/256, 256>>>(hs, hsr);
    // launch 2: transposes + ilr fused
    transpose3i_kernel<<<dim3(32,32,4), 256>>>(Wq, Wk, Wv, WT, hs, ilw, ilb);
    // launch 3: fused QKV GEMM
    dim3 gq(3*CC/128, MROWS/128);
    gemm_tf32<1><<<gq, 256>>>(hsr, WT, (float*)pX);
    // launch 4: scan (ncu capture slot)
    scan_kernel<<<BB*NHH*2, 256, SCAN_SMEM_BYTES>>>(W1, W2);
    // launch 5-6: Wo transpose + output GEMM
    transpose_kernel<<<dim3(32,32), 256>>>(Wo, WT + 3*(size_t)CC*CC);
    dim3 go(CC/128, MROWS/128);
    gemm_tf32<0><<<go, 256>>>((const float*)pZ2b, WT + 3*(size_t)CC*CC, out);
}